// round 8
// baseline (speedup 1.0000x reference)
#include <cuda_runtime.h>
#include <math.h>
#include <stdint.h>

#define BATCH 64
#define NN    256
#define MM    512
#define SIGMA 1e-6f
#define RHO   0.1f
#define ALPHA 1.6f
#define ITERS 200
#define TRI   32896   // 256*257/2
#define RR    80      // Y rows resident in SMEM (warps 0..4 fully resident)

__device__ float g_Linv[BATCH * TRI];
__device__ float g_M[BATCH * TRI];
__device__ float g_Y[BATCH * NN * MM];
__device__ float g_S[BATCH * NN];

__device__ __forceinline__ int offr(int i) { return (i * (i + 1)) >> 1; }
__constant__ int c_ti[10] = {0,1,1,2,2,2,3,3,3,3};
__constant__ int c_tj[10] = {0,0,1,0,1,2,0,1,2,3};

// K1: M = diag(P)+sigma*I+rho*A^T A (packed lower). 64x64 tiles, 4x4 regs.
__global__ __launch_bounds__(256) void k1_buildM(const float* __restrict__ Pv,
                                                 const float* __restrict__ Av)
{
    int p = blockIdx.x, b = blockIdx.y;
    int i0 = c_ti[p] * 64, j0 = c_tj[p] * 64;
    __shared__ float As[16][64], Bs[16][64];
    const float* A = Av + (size_t)b * (MM * NN);
    float acc[4][4];
#pragma unroll
    for (int a = 0; a < 4; a++)
#pragma unroll
        for (int c = 0; c < 4; c++) acc[a][c] = 0.f;
    int t = threadIdx.x, tx = t & 15, ty = t >> 4;
    for (int k0 = 0; k0 < MM; k0 += 16) {
#pragma unroll
        for (int r = 0; r < 4; r++) {
            int idx = t + 256 * r, kk = idx >> 6, ii = idx & 63;
            As[kk][ii] = A[(k0 + kk) * NN + i0 + ii];
            Bs[kk][ii] = A[(k0 + kk) * NN + j0 + ii];
        }
        __syncthreads();
#pragma unroll
        for (int kk = 0; kk < 16; kk++) {
            float a[4], c[4];
#pragma unroll
            for (int x = 0; x < 4; x++) { a[x] = As[kk][ty + 16 * x]; c[x] = Bs[kk][tx + 16 * x]; }
#pragma unroll
            for (int ii = 0; ii < 4; ii++)
#pragma unroll
                for (int jj = 0; jj < 4; jj++) acc[ii][jj] = fmaf(a[ii], c[jj], acc[ii][jj]);
        }
        __syncthreads();
    }
    float* Mb = g_M + (size_t)b * TRI;
#pragma unroll
    for (int ii = 0; ii < 4; ii++) {
        int i = i0 + ty + 16 * ii;
#pragma unroll
        for (int jj = 0; jj < 4; jj++) {
            int j = j0 + tx + 16 * jj;
            if (j <= i) {
                float vv = RHO * acc[ii][jj];
                if (i == j) vv += Pv[b * NN + i] + SIGMA;
                Mb[offr(i) + j] = vv;
            }
        }
    }
}

// K23: fused Cholesky + triangular inverse, all in SMEM. Writes g_Linv only.
__global__ __launch_bounds__(1024) void k23_chol_inv()
{
    int b = blockIdx.x, tid = threadIdx.x;
    extern __shared__ float smf[];
    float* Ls  = smf;             // TRI
    float* col = smf + TRI;       // 256
    float* cb0 = col + 256;       // 32*256
    const float* Mb = g_M + (size_t)b * TRI;
    float* Lb = g_Linv + (size_t)b * TRI;
    for (int i = tid; i < TRI; i += 1024) Ls[i] = Mb[i];
    __syncthreads();
    int lane = tid & 31, w = tid >> 5;
    for (int k = 0; k < 256; k++) {
        float dkk = Ls[offr(k) + k];
        float s = sqrtf(dkk), rinv = 1.0f / s;
        __syncthreads();
        for (int i = k + tid; i < 256; i += 1024) {
            if (i == k) { Ls[offr(k) + k] = s; col[k] = s; }
            else { float vv = Ls[offr(i) + k] * rinv; Ls[offr(i) + k] = vv; col[i] = vv; }
        }
        __syncthreads();
        for (int i = k + 1 + w; i < 256; i += 32) {
            float ci = col[i];
            float* row = Ls + offr(i);
            for (int j = k + 1 + lane; j <= i; j += 32) row[j] = fmaf(-ci, col[j], row[j]);
        }
        __syncthreads();
    }
    float* cb = cb0 + w * 256;
    for (int kc = w; kc < 256; kc += 32) {
        if (lane == 0) cb[kc] = 1.0f / Ls[offr(kc) + kc];
        __syncwarp();
        for (int i = kc + 1; i < 256; i++) {
            const float* row = Ls + offr(i);
            float s = 0.f;
            for (int j = kc + lane; j < i; j += 32) s = fmaf(row[j], cb[j], s);
#pragma unroll
            for (int o = 16; o; o >>= 1) s += __shfl_xor_sync(0xFFFFFFFFu, s, o);
            if (lane == 0) cb[i] = -s / row[i];
            __syncwarp();
        }
        for (int i = kc + lane; i < 256; i += 32) Lb[offr(i) + kc] = cb[i];
    }
}

// K4: Y[n][m] = sum_{j<=n} Linv[n][j]*A[m][j]
__global__ __launch_bounds__(256) void k4_Y(const float* __restrict__ Av)
{
    int b = blockIdx.z;
    int m0 = blockIdx.x * 64, n0 = blockIdx.y * 64;
    __shared__ float As[16][65], Bs[16][65];
    const float* Lb = g_Linv + (size_t)b * TRI;
    const float* A = Av + (size_t)b * (MM * NN);
    float acc[4][4];
#pragma unroll
    for (int a = 0; a < 4; a++)
#pragma unroll
        for (int c = 0; c < 4; c++) acc[a][c] = 0.f;
    int t = threadIdx.x, tx = t & 15, ty = t >> 4;
    int kmax = n0 + 64;
    for (int k0 = 0; k0 < kmax; k0 += 16) {
#pragma unroll
        for (int r = 0; r < 4; r++) {
            int idx = t + 256 * r, jj = idx & 15, nn = idx >> 4;
            int n = n0 + nn, j = k0 + jj;
            As[jj][nn] = (j <= n) ? Lb[offr(n) + j] : 0.f;
            Bs[jj][nn] = A[(m0 + nn) * NN + j];
        }
        __syncthreads();
#pragma unroll
        for (int jj = 0; jj < 16; jj++) {
            float a[4], c[4];
#pragma unroll
            for (int x = 0; x < 4; x++) { a[x] = As[jj][ty + 16 * x]; c[x] = Bs[jj][tx + 16 * x]; }
#pragma unroll
            for (int ii = 0; ii < 4; ii++)
#pragma unroll
                for (int cc = 0; cc < 4; cc++) acc[ii][cc] = fmaf(a[ii], c[cc], acc[ii][cc]);
        }
        __syncthreads();
    }
#pragma unroll
    for (int ii = 0; ii < 4; ii++) {
        int n = n0 + ty + 16 * ii;
#pragma unroll
        for (int cc = 0; cc < 4; cc++) {
            int m = m0 + tx + 16 * cc;
            g_Y[((size_t)b * NN + n) * MM + m] = acc[ii][cc];
        }
    }
}

// K5: 200 ADMM iterations. NO cluster. One CTA per batch (64 CTAs, 512 threads).
// Warp w owns rows [16w, 16w+16); warps 0..4 read SMEM-resident rows, 5..15 read L2.
// Groups of 4 interleaved rows: 4 concurrent load streams + interleaved shfl chains.
#define SM5_FLOATS (RR * 512 + 16 * 512 + 4 * 512 + 512)
__global__ __launch_bounds__(512, 1)
void k5_iter(const float* __restrict__ lv, const float* __restrict__ uv,
             const float* __restrict__ qv)
{
    int b = blockIdx.x;
    int tid = threadIdx.x, lane = tid & 31, w = tid >> 5;
    extern __shared__ float sm5[];
    float* sY   = sm5;                    // RR*512
    float* red  = sY + RR * 512;          // 16*512
    float* sz   = red + 16 * 512;         // 512
    float* sy   = sz + 512;               // 512
    float* sl   = sy + 512;               // 512
    float* sub  = sl + 512;               // 512
    float* sS   = sub + 512;              // 256
    float* sgre = sS + 256;               // 256

    const float* Yg = g_Y + (size_t)b * NN * MM;
    const float4* Yg4 = (const float4*)Yg;
    for (int i = tid; i < RR * 128; i += 512)
        ((float4*)sY)[i] = Yg4[i];
    sz[tid] = 0.f; sy[tid] = 0.f;
    sl[tid] = lv[b * MM + tid]; sub[tid] = uv[b * MM + tid];

    // g_n = sum_{j<=n} Linv[n][j] q[j] for this warp's 16 rows
    {
        const float* Lb = g_Linv + (size_t)b * TRI;
        const float* qb = qv + b * NN;
#pragma unroll 1
        for (int r = 0; r < 16; r++) {
            int n = w * 16 + r;
            const float* row = Lb + offr(n);
            float s = 0.f;
            for (int j = lane; j <= n; j += 32) s = fmaf(row[j], qb[j], s);
#pragma unroll
            for (int o = 16; o; o >>= 1) s += __shfl_xor_sync(0xFFFFFFFFu, s, o);
            if (lane == 0) { sgre[n] = s; sS[n] = 0.f; }
        }
    }
    __syncthreads();

    const float4* sY4 = (const float4*)sY;
    const float4* z4 = (const float4*)sz;
    const float4* yv4 = (const float4*)sy;
    float4* redw = (float4*)(red + w * 512);
    const bool res = (w < 5);   // warp-uniform residency

    for (int it = 0; it < ITERS; it++) {
        float4 ul[4];
#pragma unroll
        for (int c = 0; c < 4; c++) {
            float4 zz = z4[lane * 4 + c], yy = yv4[lane * 4 + c];
            ul[c].x = RHO * zz.x - yy.x; ul[c].y = RHO * zz.y - yy.y;
            ul[c].z = RHO * zz.z - yy.z; ul[c].w = RHO * zz.w - yy.w;
        }
        float4 acc[4];
#pragma unroll
        for (int c = 0; c < 4; c++) acc[c] = make_float4(0.f, 0.f, 0.f, 0.f);

#pragma unroll
        for (int g = 0; g < 4; g++) {
            int n0 = w * 16 + g * 4;
            float4 y[4][4];
            if (res) {
#pragma unroll
                for (int k = 0; k < 4; k++)
#pragma unroll
                    for (int c = 0; c < 4; c++)
                        y[k][c] = sY4[(size_t)(n0 + k) * 128 + lane * 4 + c];
            } else {
#pragma unroll
                for (int k = 0; k < 4; k++)
#pragma unroll
                    for (int c = 0; c < 4; c++)
                        y[k][c] = Yg4[(size_t)(n0 + k) * 128 + lane * 4 + c];
            }
            float s[4];
#pragma unroll
            for (int k = 0; k < 4; k++) {
                float t = 0.f;
#pragma unroll
                for (int c = 0; c < 4; c++)
                    t += y[k][c].x * ul[c].x + y[k][c].y * ul[c].y
                       + y[k][c].z * ul[c].z + y[k][c].w * ul[c].w;
                s[k] = t;
            }
#pragma unroll
            for (int o = 16; o; o >>= 1)
#pragma unroll
                for (int k = 0; k < 4; k++)
                    s[k] += __shfl_xor_sync(0xFFFFFFFFu, s[k], o);
#pragma unroll
            for (int k = 0; k < 4; k++) s[k] -= sgre[n0 + k];
            if (lane < 4) {
                float sv = (lane == 0) ? s[0] : (lane == 1) ? s[1]
                         : (lane == 2) ? s[2] : s[3];
                int n = n0 + lane;
                sS[n] = (1.0f - ALPHA) * sS[n] + ALPHA * sv;
            }
#pragma unroll
            for (int k = 0; k < 4; k++)
#pragma unroll
                for (int c = 0; c < 4; c++) {
                    acc[c].x = fmaf(s[k], y[k][c].x, acc[c].x);
                    acc[c].y = fmaf(s[k], y[k][c].y, acc[c].y);
                    acc[c].z = fmaf(s[k], y[k][c].z, acc[c].z);
                    acc[c].w = fmaf(s[k], y[k][c].w, acc[c].w);
                }
        }
#pragma unroll
        for (int c = 0; c < 4; c++) redw[lane * 4 + c] = acc[c];
        __syncthreads();
        {
            float zt = 0.f;
#pragma unroll
            for (int w2 = 0; w2 < 16; w2++) zt += red[w2 * 512 + tid];
            float zr = ALPHA * zt + (1.0f - ALPHA) * sz[tid];
            float zc = zr + sy[tid] * (1.0f / RHO);
            float zn = fminf(fmaxf(zc, sl[tid]), sub[tid]);
            sy[tid] = sy[tid] + RHO * (zr - zn);
            sz[tid] = zn;
        }
        __syncthreads();
    }
    if (tid < NN) g_S[b * NN + tid] = sS[tid];
}

// K6: x = Linv^T * S  -> d_out
__global__ __launch_bounds__(256) void k6_final(float* __restrict__ out)
{
    int b = blockIdx.x, tid = threadIdx.x;
    int lane = tid & 31, w = tid >> 5;
    __shared__ float sS[NN];
    __shared__ float red6[8][NN];
    sS[tid] = g_S[b * NN + tid];
    __syncthreads();
    const float* Lb = g_Linv + (size_t)b * TRI;
    float acc[8];
#pragma unroll
    for (int c = 0; c < 8; c++) acc[c] = 0.f;
    for (int n = w; n < NN; n += 8) {
        const float* row = Lb + offr(n);
        float sv = sS[n];
#pragma unroll
        for (int c = 0; c < 8; c++) {
            int i = lane + 32 * c;
            if (i <= n) acc[c] = fmaf(sv, row[i], acc[c]);
        }
    }
#pragma unroll
    for (int c = 0; c < 8; c++) red6[w][lane + 32 * c] = acc[c];
    __syncthreads();
    float x = 0.f;
#pragma unroll
    for (int w2 = 0; w2 < 8; w2++) x += red6[w2][tid];
    out[b * NN + tid] = x;
}

extern "C" void kernel_launch(void* const* d_in, const int* in_sizes, int n_in,
                              void* d_out, int out_size)
{
    const float* P = (const float*)d_in[0];
    const float* q = (const float*)d_in[1];
    const float* A = (const float*)d_in[2];
    const float* l = (const float*)d_in[3];
    const float* u = (const float*)d_in[4];
    float* out = (float*)d_out;

    int smem_k23 = (TRI + 256 + 32 * 256) * 4;   // 165,376 B
    int smem_k5 = SM5_FLOATS * 4;                // 206,848 B
    cudaFuncSetAttribute(k23_chol_inv, cudaFuncAttributeMaxDynamicSharedMemorySize, smem_k23);
    cudaFuncSetAttribute(k5_iter, cudaFuncAttributeMaxDynamicSharedMemorySize, smem_k5);

    k1_buildM<<<dim3(10, BATCH), 256>>>(P, A);
    k23_chol_inv<<<BATCH, 1024, smem_k23>>>();
    k4_Y<<<dim3(8, 4, BATCH), 256>>>(A);
    k5_iter<<<BATCH, 512, smem_k5>>>(l, u, q);
    k6_final<<<BATCH, 256>>>(out);
}

// round 9
// speedup vs baseline: 1.3082x; 1.3082x over previous
#include <cuda_runtime.h>
#include <cooperative_groups.h>
#include <math.h>
#include <stdint.h>

namespace cg = cooperative_groups;

#define BATCH 64
#define NN    256
#define MM    512
#define SIGMA 1e-6f
#define RHO   0.1f
#define ALPHA 1.6f
#define ITERS 200
#define TRI   32896   // 256*257/2
#define RR    96      // Y rows resident in SMEM per half (of 128): groups g=0..2

__device__ float g_Linv[BATCH * TRI];
__device__ float g_M[BATCH * TRI];
__device__ float g_Y[BATCH * NN * MM];
__device__ float g_S[BATCH * NN];

__device__ __forceinline__ int offr(int i) { return (i * (i + 1)) >> 1; }
__constant__ int c_ti[10] = {0,1,1,2,2,2,3,3,3,3};
__constant__ int c_tj[10] = {0,0,1,0,1,2,0,1,2,3};

__device__ __forceinline__ uint32_t smem_u32(const void* p) {
    uint32_t a;
    asm("{ .reg .u64 t; cvta.to.shared.u64 t, %1; cvt.u32.u64 %0, t; }"
        : "=r"(a) : "l"(p));
    return a;
}

// K1: M = diag(P)+sigma*I+rho*A^T A (packed lower). 64x64 tiles, 4x4 regs.
__global__ __launch_bounds__(256) void k1_buildM(const float* __restrict__ Pv,
                                                 const float* __restrict__ Av)
{
    int p = blockIdx.x, b = blockIdx.y;
    int i0 = c_ti[p] * 64, j0 = c_tj[p] * 64;
    __shared__ float As[16][64], Bs[16][64];
    const float* A = Av + (size_t)b * (MM * NN);
    float acc[4][4];
#pragma unroll
    for (int a = 0; a < 4; a++)
#pragma unroll
        for (int c = 0; c < 4; c++) acc[a][c] = 0.f;
    int t = threadIdx.x, tx = t & 15, ty = t >> 4;
    for (int k0 = 0; k0 < MM; k0 += 16) {
#pragma unroll
        for (int r = 0; r < 4; r++) {
            int idx = t + 256 * r, kk = idx >> 6, ii = idx & 63;
            As[kk][ii] = A[(k0 + kk) * NN + i0 + ii];
            Bs[kk][ii] = A[(k0 + kk) * NN + j0 + ii];
        }
        __syncthreads();
#pragma unroll
        for (int kk = 0; kk < 16; kk++) {
            float a[4], c[4];
#pragma unroll
            for (int x = 0; x < 4; x++) { a[x] = As[kk][ty + 16 * x]; c[x] = Bs[kk][tx + 16 * x]; }
#pragma unroll
            for (int ii = 0; ii < 4; ii++)
#pragma unroll
                for (int jj = 0; jj < 4; jj++) acc[ii][jj] = fmaf(a[ii], c[jj], acc[ii][jj]);
        }
        __syncthreads();
    }
    float* Mb = g_M + (size_t)b * TRI;
#pragma unroll
    for (int ii = 0; ii < 4; ii++) {
        int i = i0 + ty + 16 * ii;
#pragma unroll
        for (int jj = 0; jj < 4; jj++) {
            int j = j0 + tx + 16 * jj;
            if (j <= i) {
                float vv = RHO * acc[ii][jj];
                if (i == j) vv += Pv[b * NN + i] + SIGMA;
                Mb[offr(i) + j] = vv;
            }
        }
    }
}

// K23: fused Cholesky + triangular inverse, all in SMEM. Writes g_Linv only.
__global__ __launch_bounds__(1024) void k23_chol_inv()
{
    int b = blockIdx.x, tid = threadIdx.x;
    extern __shared__ float smf[];
    float* Ls  = smf;             // TRI
    float* col = smf + TRI;       // 256
    float* cb0 = col + 256;       // 32*256
    const float* Mb = g_M + (size_t)b * TRI;
    float* Lb = g_Linv + (size_t)b * TRI;
    for (int i = tid; i < TRI; i += 1024) Ls[i] = Mb[i];
    __syncthreads();
    int lane = tid & 31, w = tid >> 5;
    for (int k = 0; k < 256; k++) {
        float dkk = Ls[offr(k) + k];
        float s = sqrtf(dkk), rinv = 1.0f / s;
        __syncthreads();
        for (int i = k + tid; i < 256; i += 1024) {
            if (i == k) { Ls[offr(k) + k] = s; col[k] = s; }
            else { float vv = Ls[offr(i) + k] * rinv; Ls[offr(i) + k] = vv; col[i] = vv; }
        }
        __syncthreads();
        for (int i = k + 1 + w; i < 256; i += 32) {
            float ci = col[i];
            float* row = Ls + offr(i);
            for (int j = k + 1 + lane; j <= i; j += 32) row[j] = fmaf(-ci, col[j], row[j]);
        }
        __syncthreads();
    }
    float* cb = cb0 + w * 256;
    for (int kc = w; kc < 256; kc += 32) {
        if (lane == 0) cb[kc] = 1.0f / Ls[offr(kc) + kc];
        __syncwarp();
        for (int i = kc + 1; i < 256; i++) {
            const float* row = Ls + offr(i);
            float s = 0.f;
            for (int j = kc + lane; j < i; j += 32) s = fmaf(row[j], cb[j], s);
#pragma unroll
            for (int o = 16; o; o >>= 1) s += __shfl_xor_sync(0xFFFFFFFFu, s, o);
            if (lane == 0) cb[i] = -s / row[i];
            __syncwarp();
        }
        for (int i = kc + lane; i < 256; i += 32) Lb[offr(i) + kc] = cb[i];
    }
}

// K4: Y[n][m] = sum_{j<=n} Linv[n][j]*A[m][j]
__global__ __launch_bounds__(256) void k4_Y(const float* __restrict__ Av)
{
    int b = blockIdx.z;
    int m0 = blockIdx.x * 64, n0 = blockIdx.y * 64;
    __shared__ float As[16][65], Bs[16][65];
    const float* Lb = g_Linv + (size_t)b * TRI;
    const float* A = Av + (size_t)b * (MM * NN);
    float acc[4][4];
#pragma unroll
    for (int a = 0; a < 4; a++)
#pragma unroll
        for (int c = 0; c < 4; c++) acc[a][c] = 0.f;
    int t = threadIdx.x, tx = t & 15, ty = t >> 4;
    int kmax = n0 + 64;
    for (int k0 = 0; k0 < kmax; k0 += 16) {
#pragma unroll
        for (int r = 0; r < 4; r++) {
            int idx = t + 256 * r, jj = idx & 15, nn = idx >> 4;
            int n = n0 + nn, j = k0 + jj;
            As[jj][nn] = (j <= n) ? Lb[offr(n) + j] : 0.f;
            Bs[jj][nn] = A[(m0 + nn) * NN + j];
        }
        __syncthreads();
#pragma unroll
        for (int jj = 0; jj < 16; jj++) {
            float a[4], c[4];
#pragma unroll
            for (int x = 0; x < 4; x++) { a[x] = As[jj][ty + 16 * x]; c[x] = Bs[jj][tx + 16 * x]; }
#pragma unroll
            for (int ii = 0; ii < 4; ii++)
#pragma unroll
                for (int cc = 0; cc < 4; cc++) acc[ii][cc] = fmaf(a[ii], c[cc], acc[ii][cc]);
        }
        __syncthreads();
    }
#pragma unroll
    for (int ii = 0; ii < 4; ii++) {
        int n = n0 + ty + 16 * ii;
#pragma unroll
        for (int cc = 0; cc < 4; cc++) {
            int m = m0 + tx + 16 * cc;
            g_Y[((size_t)b * NN + n) * MM + m] = acc[ii][cc];
        }
    }
}

// K5: 200 ADMM iterations. Cluster-2 per batch, 256 threads/CTA (8 warps -> 255-reg
// budget, NO spills). CTA owns 128 rows; warp w owns rows n = w + 8k (k=0..15);
// groups of 4 rows; groups g=0..2 (k<12 -> rows 0..95) SMEM-resident, g=3 from L2.
#define SM5_FLOATS (4 + RR * 512 + 8 * 512 + 4 * 512 + 2 * 512 + 256)
__global__ __cluster_dims__(2, 1, 1) __launch_bounds__(256, 1)
void k5_iter(const float* __restrict__ lv, const float* __restrict__ uv,
             const float* __restrict__ qv)
{
    cg::cluster_group cluster = cg::this_cluster();
    int b = blockIdx.x >> 1, half = blockIdx.x & 1;
    int tid = threadIdx.x, lane = tid & 31, w = tid >> 5;   // w in 0..7
    extern __shared__ float sm5[];
    float* mbf  = sm5;                    // 2 x u64 mbarriers
    float* sY   = sm5 + 4;                // RR*512
    float* red  = sY + RR * 512;          // 8*512
    float* sz   = red + 8 * 512;          // 512
    float* sy   = sz + 512;               // 512
    float* sl   = sy + 512;               // 512
    float* sub  = sl + 512;               // 512
    float* sbuf = sub + 512;              // 2*512 (peer writes here)
    float* sS   = sbuf + 1024;            // 128
    float* sgre = sS + 128;               // 128

    uint32_t mb_u32 = smem_u32(mbf);
    if (tid == 0) {
        asm volatile("mbarrier.init.shared.b64 [%0], %1;" :: "r"(mb_u32), "r"(1) : "memory");
        asm volatile("mbarrier.init.shared.b64 [%0], %1;" :: "r"(mb_u32 + 8), "r"(1) : "memory");
    }

    const float* Yg = g_Y + ((size_t)b * NN + half * 128) * MM;
    const float4* Yg4 = (const float4*)Yg;
    for (int i = tid; i < RR * 128; i += 256)
        ((float4*)sY)[i] = Yg4[i];
    sz[tid] = 0.f; sy[tid] = 0.f;
    sz[tid + 256] = 0.f; sy[tid + 256] = 0.f;
    sl[tid] = lv[b * MM + tid]; sub[tid] = uv[b * MM + tid];
    sl[tid + 256] = lv[b * MM + tid + 256]; sub[tid + 256] = uv[b * MM + tid + 256];

    // g_n = sum_{j<=n} Linv[n][j] q[j] for this warp's 16 rows (n_local = w + 8k)
    {
        const float* Lb = g_Linv + (size_t)b * TRI;
        const float* qb = qv + b * NN;
#pragma unroll 1
        for (int k = 0; k < 16; k++) {
            int nl = w + 8 * k;
            int ng = half * 128 + nl;
            const float* row = Lb + offr(ng);
            float s = 0.f;
            for (int j = lane; j <= ng; j += 32) s = fmaf(row[j], qb[j], s);
#pragma unroll
            for (int o = 16; o; o >>= 1) s += __shfl_xor_sync(0xFFFFFFFFu, s, o);
            if (lane == 0) { sgre[nl] = s; sS[nl] = 0.f; }
        }
    }
    cluster.sync();   // barrier init + staging visible cluster-wide

    uint32_t peer = (uint32_t)(half ^ 1);
    float* peerbuf = cluster.map_shared_rank(sbuf, peer);
    const float4* sY4 = (const float4*)sY;
    const float4* z4 = (const float4*)sz;
    const float4* yv4 = (const float4*)sy;
    float4* redw = (float4*)(red + w * 512);

    for (int it = 0; it < ITERS; it++) {
        float4 ul[4];
#pragma unroll
        for (int c = 0; c < 4; c++) {
            float4 zz = z4[lane * 4 + c], yy = yv4[lane * 4 + c];
            ul[c].x = RHO * zz.x - yy.x; ul[c].y = RHO * zz.y - yy.y;
            ul[c].z = RHO * zz.z - yy.z; ul[c].w = RHO * zz.w - yy.w;
        }
        float4 acc[4];
#pragma unroll
        for (int c = 0; c < 4; c++) acc[c] = make_float4(0.f, 0.f, 0.f, 0.f);

#pragma unroll
        for (int g = 0; g < 4; g++) {
            // rows n_j = w + 8*(4g+j), j=0..3 ; resident iff g<3 (rows < 96)
            float4 y[4][4];
            if (g < 3) {
#pragma unroll
                for (int j = 0; j < 4; j++) {
                    int n = w + 8 * (4 * g + j);
#pragma unroll
                    for (int c = 0; c < 4; c++)
                        y[j][c] = sY4[(size_t)n * 128 + lane * 4 + c];
                }
            } else {
#pragma unroll
                for (int j = 0; j < 4; j++) {
                    int n = w + 8 * (4 * g + j);
#pragma unroll
                    for (int c = 0; c < 4; c++)
                        y[j][c] = Yg4[(size_t)n * 128 + lane * 4 + c];
                }
            }
            float s[4];
#pragma unroll
            for (int j = 0; j < 4; j++) {
                float t = 0.f;
#pragma unroll
                for (int c = 0; c < 4; c++)
                    t += y[j][c].x * ul[c].x + y[j][c].y * ul[c].y
                       + y[j][c].z * ul[c].z + y[j][c].w * ul[c].w;
                s[j] = t;
            }
#pragma unroll
            for (int o = 16; o; o >>= 1)
#pragma unroll
                for (int j = 0; j < 4; j++)
                    s[j] += __shfl_xor_sync(0xFFFFFFFFu, s[j], o);
#pragma unroll
            for (int j = 0; j < 4; j++) s[j] -= sgre[w + 8 * (4 * g + j)];
            if (lane < 4) {
                float sv = (lane == 0) ? s[0] : (lane == 1) ? s[1]
                         : (lane == 2) ? s[2] : s[3];
                int n = w + 8 * (4 * g + lane);
                sS[n] = (1.0f - ALPHA) * sS[n] + ALPHA * sv;
            }
#pragma unroll
            for (int j = 0; j < 4; j++)
#pragma unroll
                for (int c = 0; c < 4; c++) {
                    acc[c].x = fmaf(s[j], y[j][c].x, acc[c].x);
                    acc[c].y = fmaf(s[j], y[j][c].y, acc[c].y);
                    acc[c].z = fmaf(s[j], y[j][c].z, acc[c].z);
                    acc[c].w = fmaf(s[j], y[j][c].w, acc[c].w);
                }
        }
#pragma unroll
        for (int c = 0; c < 4; c++) redw[lane * 4 + c] = acc[c];
        __syncthreads();
        float p0 = 0.f, p1 = 0.f;
#pragma unroll
        for (int w2 = 0; w2 < 8; w2++) {
            p0 += red[w2 * 512 + tid];
            p1 += red[w2 * 512 + tid + 256];
        }
        int slot = it & 1;
        uint32_t par = (uint32_t)((it >> 1) & 1);
        peerbuf[slot * 512 + tid] = p0;
        peerbuf[slot * 512 + tid + 256] = p1;
        __syncthreads();
        if (tid == 0) {
            asm volatile("fence.acq_rel.cluster;" ::: "memory");
            asm volatile(
                "{ .reg .b32 rem; mapa.shared::cluster.u32 rem, %0, %1;\n\t"
                "mbarrier.arrive.release.cluster.shared::cluster.b64 _, [rem]; }"
                :: "r"(mb_u32 + 8 * slot), "r"(peer) : "memory");
        }
        {
            uint32_t addr = mb_u32 + 8 * slot, done;
            asm volatile(
                "{ .reg .pred p;\n\t"
                "mbarrier.try_wait.parity.acquire.cluster.shared::cta.b64 p, [%1], %2;\n\t"
                "selp.b32 %0, 1, 0, p; }"
                : "=r"(done) : "r"(addr), "r"(par) : "memory");
            if (!done) {
                asm volatile(
                    "{ .reg .pred P1;\n\t"
                    "WL_%=:\n\t"
                    "mbarrier.try_wait.parity.acquire.cluster.shared::cta.b64 P1, [%0], %1, 0x989680;\n\t"
                    "@P1 bra.uni WD_%=;\n\t"
                    "bra.uni WL_%=;\n\t"
                    "WD_%=: }"
                    :: "r"(addr), "r"(par) : "memory");
            }
        }
#pragma unroll
        for (int h = 0; h < 2; h++) {
            int m = tid + 256 * h;
            float zt = (h == 0 ? p0 : p1) + sbuf[slot * 512 + m];
            float zr = ALPHA * zt + (1.0f - ALPHA) * sz[m];
            float zc = zr + sy[m] * (1.0f / RHO);
            float zn = fminf(fmaxf(zc, sl[m]), sub[m]);
            sy[m] = sy[m] + RHO * (zr - zn);
            sz[m] = zn;
        }
        __syncthreads();   // sz/sy stable before next iteration's ul read
    }
    if (tid < 128) g_S[b * NN + half * 128 + tid] = sS[tid];
    cluster.sync();   // don't exit while peer may still write our sbuf
}

// K6: x = Linv^T * S  -> d_out
__global__ __launch_bounds__(256) void k6_final(float* __restrict__ out)
{
    int b = blockIdx.x, tid = threadIdx.x;
    int lane = tid & 31, w = tid >> 5;
    __shared__ float sS[NN];
    __shared__ float red6[8][NN];
    sS[tid] = g_S[b * NN + tid];
    __syncthreads();
    const float* Lb = g_Linv + (size_t)b * TRI;
    float acc[8];
#pragma unroll
    for (int c = 0; c < 8; c++) acc[c] = 0.f;
    for (int n = w; n < NN; n += 8) {
        const float* row = Lb + offr(n);
        float sv = sS[n];
#pragma unroll
        for (int c = 0; c < 8; c++) {
            int i = lane + 32 * c;
            if (i <= n) acc[c] = fmaf(sv, row[i], acc[c]);
        }
    }
#pragma unroll
    for (int c = 0; c < 8; c++) red6[w][lane + 32 * c] = acc[c];
    __syncthreads();
    float x = 0.f;
#pragma unroll
    for (int w2 = 0; w2 < 8; w2++) x += red6[w2][tid];
    out[b * NN + tid] = x;
}

extern "C" void kernel_launch(void* const* d_in, const int* in_sizes, int n_in,
                              void* d_out, int out_size)
{
    const float* P = (const float*)d_in[0];
    const float* q = (const float*)d_in[1];
    const float* A = (const float*)d_in[2];
    const float* l = (const float*)d_in[3];
    const float* u = (const float*)d_in[4];
    float* out = (float*)d_out;

    int smem_k23 = (TRI + 256 + 32 * 256) * 4;   // 165,376 B
    int smem_k5 = SM5_FLOATS * 4;                // 226,320 B
    cudaFuncSetAttribute(k23_chol_inv, cudaFuncAttributeMaxDynamicSharedMemorySize, smem_k23);
    cudaFuncSetAttribute(k5_iter, cudaFuncAttributeMaxDynamicSharedMemorySize, smem_k5);

    k1_buildM<<<dim3(10, BATCH), 256>>>(P, A);
    k23_chol_inv<<<BATCH, 1024, smem_k23>>>();
    k4_Y<<<dim3(8, 4, BATCH), 256>>>(A);
    k5_iter<<<BATCH * 2, 256, smem_k5>>>(l, u, q);
    k6_final<<<BATCH, 256>>>(out);
}

// round 11
// speedup vs baseline: 1.5433x; 1.1797x over previous
#include <cuda_runtime.h>
#include <cooperative_groups.h>
#include <math.h>
#include <stdint.h>

namespace cg = cooperative_groups;

#define BATCH 64
#define NN    256
#define MM    512
#define SIGMA 1e-6f
#define RHO   0.1f
#define ALPHA 1.6f
#define ITERS 200
#define TRI   32896   // 256*257/2
#define RR    80      // Y rows resident in SMEM per half-CTA (of 128)

__device__ float g_Linv[BATCH * TRI];
__device__ float g_M[BATCH * TRI];
__device__ float g_Y[BATCH * NN * MM];
__device__ float g_S[BATCH * NN];

__device__ __forceinline__ int offr(int i) { return (i * (i + 1)) >> 1; }
__constant__ int c_ti[10] = {0,1,1,2,2,2,3,3,3,3};
__constant__ int c_tj[10] = {0,0,1,0,1,2,0,1,2,3};

__device__ __forceinline__ uint32_t smem_u32(const void* p) {
    uint32_t a;
    asm("{ .reg .u64 t; cvta.to.shared.u64 t, %1; cvt.u32.u64 %0, t; }"
        : "=r"(a) : "l"(p));
    return a;
}

// K1: M = diag(P)+sigma*I+rho*A^T A (packed lower). 64x64 tiles, 4x4 regs.
__global__ __launch_bounds__(256) void k1_buildM(const float* __restrict__ Pv,
                                                 const float* __restrict__ Av)
{
    int p = blockIdx.x, b = blockIdx.y;
    int i0 = c_ti[p] * 64, j0 = c_tj[p] * 64;
    __shared__ float As[16][64], Bs[16][64];
    const float* A = Av + (size_t)b * (MM * NN);
    float acc[4][4];
#pragma unroll
    for (int a = 0; a < 4; a++)
#pragma unroll
        for (int c = 0; c < 4; c++) acc[a][c] = 0.f;
    int t = threadIdx.x, tx = t & 15, ty = t >> 4;
    for (int k0 = 0; k0 < MM; k0 += 16) {
#pragma unroll
        for (int r = 0; r < 4; r++) {
            int idx = t + 256 * r, kk = idx >> 6, ii = idx & 63;
            As[kk][ii] = A[(k0 + kk) * NN + i0 + ii];
            Bs[kk][ii] = A[(k0 + kk) * NN + j0 + ii];
        }
        __syncthreads();
#pragma unroll
        for (int kk = 0; kk < 16; kk++) {
            float a[4], c[4];
#pragma unroll
            for (int x = 0; x < 4; x++) { a[x] = As[kk][ty + 16 * x]; c[x] = Bs[kk][tx + 16 * x]; }
#pragma unroll
            for (int ii = 0; ii < 4; ii++)
#pragma unroll
                for (int jj = 0; jj < 4; jj++) acc[ii][jj] = fmaf(a[ii], c[jj], acc[ii][jj]);
        }
        __syncthreads();
    }
    float* Mb = g_M + (size_t)b * TRI;
#pragma unroll
    for (int ii = 0; ii < 4; ii++) {
        int i = i0 + ty + 16 * ii;
#pragma unroll
        for (int jj = 0; jj < 4; jj++) {
            int j = j0 + tx + 16 * jj;
            if (j <= i) {
                float vv = RHO * acc[ii][jj];
                if (i == j) vv += Pv[b * NN + i] + SIGMA;
                Mb[offr(i) + j] = vv;
            }
        }
    }
}

// K23: BLOCKED Cholesky + BLOCKED triangular inverse. 512 threads, NB=32.
__global__ __launch_bounds__(512) void k23_blocked()
{
    int b = blockIdx.x, tid = threadIdx.x;
    int lane = tid & 31, w = tid >> 5;   // 16 warps
    extern __shared__ float smf[];
    float* Ls   = smf;                   // TRI
    float* Dnv  = smf + TRI;             // 8*32*33: Dnv[J][c*33+i] = (L_JJ^-1)[i][c]
    float* Tmp  = Dnv + 8 * 32 * 33;     // 8*32*33: Tmp[J][r*33+c]
    const float* Mb = g_M + (size_t)b * TRI;
    float* Lb = g_Linv + (size_t)b * TRI;

    for (int i = tid; i < TRI; i += 512) Ls[i] = Mb[i];
    for (int i = tid; i < 8 * 32 * 33; i += 512) Dnv[i] = 0.f;
    __syncthreads();

    // ---------------- blocked Cholesky ----------------
    for (int K = 0; K < 8; K++) {
        int ib = K * 32;
        // 1. diag block factor (warp 0)
        if (w == 0) {
            for (int k = 0; k < 32; k++) {
                int ik = ib + k;
                float piv = Ls[offr(ik) + ik];
                float s = sqrtf(piv), rinv = 1.0f / s;
                float v = 0.f;
                if (lane == k) Ls[offr(ik) + ik] = s;
                if (lane > k) {
                    v = Ls[offr(ib + lane) + ik] * rinv;
                    Ls[offr(ib + lane) + ik] = v;
                }
                __syncwarp();
                int rowo = offr(ib + lane) + ib;
                for (int c = k + 1; c < 32; c++) {
                    float vc = __shfl_sync(0xffffffffu, v, c);
                    if (lane > k && c <= lane) Ls[rowo + c] -= v * vc;
                }
                __syncwarp();
            }
        }
        __syncthreads();
        // 2. panel TRSM: thread-per-row forward substitution (x L_KK^T = a)
        int rows_below = 256 - (K + 1) * 32;
        if (tid < rows_below) {
            int i = (K + 1) * 32 + tid;
            int rb = offr(i) + ib;
            float x[32];
#pragma unroll
            for (int j = 0; j < 32; j++) {
                float xj = Ls[rb + j];
#pragma unroll
                for (int kk = 0; kk < j; kk++)
                    xj -= x[kk] * Ls[offr(ib + j) + ib + kk];
                x[j] = xj / Ls[offr(ib + j) + ib + j];
            }
#pragma unroll
            for (int j = 0; j < 32; j++) Ls[rb + j] = x[j];
        }
        __syncthreads();
        // 3. trailing SYRK: warp-per-tile, lane = column
        if (rows_below > 0) {
            int nb2 = 7 - K;
            int T = nb2 * (nb2 + 1) / 2;
            for (int t = w; t < T; t += 16) {
                int bi2 = 0;
                while ((bi2 + 1) * (bi2 + 2) / 2 <= t) bi2++;
                int bj2 = t - bi2 * (bi2 + 1) / 2;
                int I = K + 1 + bi2, J = K + 1 + bj2;
                float lj[32];
                int cj = offr(J * 32 + lane) + ib;
#pragma unroll
                for (int k = 0; k < 32; k++) lj[k] = Ls[cj + k];
                for (int r = 0; r < 32; r++) {
                    int ri = offr(I * 32 + r);
                    float acc = Ls[ri + J * 32 + lane];   // OOB-row read ok (in-array), write-guarded
                    int rb2 = ri + ib;
#pragma unroll
                    for (int k = 0; k < 32; k++)
                        acc -= Ls[rb2 + k] * lj[k];
                    if (I != J || lane <= r) Ls[ri + J * 32 + lane] = acc;
                }
            }
        }
        __syncthreads();
    }

    // ---------------- blocked trinv ----------------
    // D_J = L_JJ^{-1}: warp J, lane c owns column c (lane-private, no shfl)
    if (w < 8) {
        int J = w, jb = J * 32;
        float* D = Dnv + J * 32 * 33;
        for (int i = 0; i < 32; i++) {
            float Lii = Ls[offr(jb + i) + jb + i];
            if (i == lane) {
                D[lane * 33 + i] = 1.0f / Lii;
            } else if (i > lane) {
                float s = 0.f;
                for (int k = lane; k < i; k++)
                    s += Ls[offr(jb + i) + jb + k] * D[lane * 33 + k];
                D[lane * 33 + i] = -s / Lii;
            }
        }
        // write diag block of Linv (lower part only; upper is structurally 0)
        for (int i = 0; i < 32; i++)
            if (lane <= i) Lb[offr(jb + i) + jb + lane] = D[lane * 33 + i];
    }
    __syncthreads();

    // column phase: Linv[I][J] = -D_I * (sum_{K2=J}^{I-1} L[I][K2] Linv[K2][J])
    // pair of warps per J: J = w&7, half h = w>>3 owns rows [16h,16h+16)
    {
        int J = w & 7, h = w >> 3, jb = J * 32;
        int r0 = h * 16;
        float* TJ = Tmp + J * 32 * 33;
        for (int I = J + 1; I < 8; I++) {
            int ibb = I * 32;
            float accr[16];
#pragma unroll
            for (int r2 = 0; r2 < 16; r2++) accr[r2] = 0.f;
            for (int K2 = J; K2 < I; K2++) {
                int kb = K2 * 32;
                float lv[32];
#pragma unroll
                for (int k = 0; k < 32; k++) {
                    // FIX(R10): K2==J is the packed-triangular diag block of Linv;
                    // entries with lane>k are structurally zero and MUST NOT be
                    // read (offr(kb+k)+jb+lane would alias the next packed row).
                    float val = 0.f;
                    if (K2 != J || lane <= k)
                        val = Lb[offr(kb + k) + jb + lane];
                    lv[k] = val;
                }
#pragma unroll
                for (int r2 = 0; r2 < 16; r2++) {
                    int ro = offr(ibb + r0 + r2) + kb;
                    float a = accr[r2];
#pragma unroll
                    for (int k = 0; k < 32; k++)
                        a = fmaf(Ls[ro + k], lv[k], a);     // broadcast * reg
                    accr[r2] = a;
                }
            }
#pragma unroll
            for (int r2 = 0; r2 < 16; r2++)
                TJ[(r0 + r2) * 33 + lane] = accr[r2];
            asm volatile("bar.sync %0, %1;" :: "r"(J + 1), "r"(64) : "memory");
            {
                float tv[32];
#pragma unroll
                for (int s2 = 0; s2 < 32; s2++) tv[s2] = TJ[s2 * 33 + lane];
                float* DI = Dnv + I * 32 * 33;
#pragma unroll
                for (int r2 = 0; r2 < 16; r2++) {
                    float o = 0.f;
#pragma unroll
                    for (int s2 = 0; s2 < 32; s2++)
                        o = fmaf(DI[s2 * 33 + (r0 + r2)], tv[s2], o);  // broadcast * reg
                    Lb[offr(ibb + r0 + r2) + jb + lane] = -o;
                }
            }
            asm volatile("bar.sync %0, %1;" :: "r"(J + 1), "r"(64) : "memory");
        }
    }
}

// K4: Y[n][m] = sum_{j<=n} Linv[n][j]*A[m][j]
__global__ __launch_bounds__(256) void k4_Y(const float* __restrict__ Av)
{
    int b = blockIdx.z;
    int m0 = blockIdx.x * 64, n0 = blockIdx.y * 64;
    __shared__ float As[16][65], Bs[16][65];
    const float* Lb = g_Linv + (size_t)b * TRI;
    const float* A = Av + (size_t)b * (MM * NN);
    float acc[4][4];
#pragma unroll
    for (int a = 0; a < 4; a++)
#pragma unroll
        for (int c = 0; c < 4; c++) acc[a][c] = 0.f;
    int t = threadIdx.x, tx = t & 15, ty = t >> 4;
    int kmax = n0 + 64;
    for (int k0 = 0; k0 < kmax; k0 += 16) {
#pragma unroll
        for (int r = 0; r < 4; r++) {
            int idx = t + 256 * r, jj = idx & 15, nn = idx >> 4;
            int n = n0 + nn, j = k0 + jj;
            As[jj][nn] = (j <= n) ? Lb[offr(n) + j] : 0.f;
            Bs[jj][nn] = A[(m0 + nn) * NN + j];
        }
        __syncthreads();
#pragma unroll
        for (int jj = 0; jj < 16; jj++) {
            float a[4], c[4];
#pragma unroll
            for (int x = 0; x < 4; x++) { a[x] = As[jj][ty + 16 * x]; c[x] = Bs[jj][tx + 16 * x]; }
#pragma unroll
            for (int ii = 0; ii < 4; ii++)
#pragma unroll
                for (int cc = 0; cc < 4; cc++) acc[ii][cc] = fmaf(a[ii], c[cc], acc[ii][cc]);
        }
        __syncthreads();
    }
#pragma unroll
    for (int ii = 0; ii < 4; ii++) {
        int n = n0 + ty + 16 * ii;
#pragma unroll
        for (int cc = 0; cc < 4; cc++) {
            int m = m0 + tx + 16 * cc;
            g_Y[((size_t)b * NN + n) * MM + m] = acc[ii][cc];
        }
    }
}

// ---- K5 batched row group: dots first, then interleaved butterflies ----
template<int R0, int CNT>
__device__ __forceinline__ void row_group(int w, int lane,
    const float4* __restrict__ sY4, const float4* __restrict__ Yg4,
    const float4 ul[4], float4 acc[4], const float gre[8], float Sreg[8])
{
    float4 y[CNT][4];
#pragma unroll
    for (int k = 0; k < CNT; k++) {
        int n = w + 16 * (R0 + k);
        const float4* src = ((R0 + k) <= 4) ? (sY4 + (size_t)n * 128)
                                            : (Yg4 + (size_t)n * 128);
#pragma unroll
        for (int c = 0; c < 4; c++) y[k][c] = src[lane * 4 + c];
    }
    float s[CNT];
#pragma unroll
    for (int k = 0; k < CNT; k++) {
        float t = 0.f;
#pragma unroll
        for (int c = 0; c < 4; c++)
            t += y[k][c].x * ul[c].x + y[k][c].y * ul[c].y
               + y[k][c].z * ul[c].z + y[k][c].w * ul[c].w;
        s[k] = t;
    }
#pragma unroll
    for (int o = 16; o; o >>= 1)
#pragma unroll
        for (int k = 0; k < CNT; k++)
            s[k] += __shfl_xor_sync(0xFFFFFFFFu, s[k], o);
#pragma unroll
    for (int k = 0; k < CNT; k++) {
        s[k] -= gre[R0 + k];
        Sreg[R0 + k] = (1.0f - ALPHA) * Sreg[R0 + k] + ALPHA * s[k];
#pragma unroll
        for (int c = 0; c < 4; c++) {
            acc[c].x = fmaf(s[k], y[k][c].x, acc[c].x);
            acc[c].y = fmaf(s[k], y[k][c].y, acc[c].y);
            acc[c].z = fmaf(s[k], y[k][c].z, acc[c].z);
            acc[c].w = fmaf(s[k], y[k][c].w, acc[c].w);
        }
    }
}

// K5: 200 ADMM iterations. Cluster-2 per batch; 80/128 rows SMEM-resident. (R6 best)
#define SM5_FLOATS (4 + RR * 512 + 16 * 512 + 4 * 512 + 2 * 512)
__global__ __cluster_dims__(2, 1, 1) __launch_bounds__(512, 1)
void k5_iter(const float* __restrict__ lv, const float* __restrict__ uv,
             const float* __restrict__ qv)
{
    cg::cluster_group cluster = cg::this_cluster();
    int b = blockIdx.x >> 1, half = blockIdx.x & 1;
    int tid = threadIdx.x, lane = tid & 31, w = tid >> 5;
    extern __shared__ float sm5[];
    float* mbf  = sm5;
    float* sY   = sm5 + 4;
    float* red  = sY + RR * 512;
    float* sz   = red + 16 * 512;
    float* sy   = sz + 512;
    float* sl   = sy + 512;
    float* sub  = sl + 512;
    float* sbuf = sub + 512;

    uint32_t mb_u32 = smem_u32(mbf);
    if (tid == 0) {
        asm volatile("mbarrier.init.shared.b64 [%0], %1;" :: "r"(mb_u32), "r"(1) : "memory");
        asm volatile("mbarrier.init.shared.b64 [%0], %1;" :: "r"(mb_u32 + 8), "r"(1) : "memory");
    }

    const float* Yg = g_Y + ((size_t)b * NN + half * 128) * MM;
    const float4* Yg4 = (const float4*)Yg;
    for (int i = tid; i < RR * 128; i += 512)
        ((float4*)sY)[i] = Yg4[i];
    sz[tid] = 0.f; sy[tid] = 0.f;
    sl[tid] = lv[b * MM + tid]; sub[tid] = uv[b * MM + tid];

    float Sreg[8], gre[8];
    {
        const float* Lb = g_Linv + (size_t)b * TRI;
        const float* qb = qv + b * NN;
#pragma unroll 1
        for (int r = 0; r < 8; r++) {
            int ng = half * 128 + w + 16 * r;
            const float* row = Lb + offr(ng);
            float s = 0.f;
            for (int j = lane; j <= ng; j += 32) s = fmaf(row[j], qb[j], s);
#pragma unroll
            for (int o = 16; o; o >>= 1) s += __shfl_xor_sync(0xFFFFFFFFu, s, o);
            gre[r] = s;
            Sreg[r] = 0.f;
        }
    }
    cluster.sync();

    uint32_t peer = (uint32_t)(half ^ 1);
    float* peerbuf = cluster.map_shared_rank(sbuf, peer);
    const float4* sY4 = (const float4*)sY;
    const float4* z4 = (const float4*)sz;
    const float4* yv4 = (const float4*)sy;
    float4* redw = (float4*)(red + w * 512);

    for (int it = 0; it < ITERS; it++) {
        __syncthreads();
        float4 ul[4];
#pragma unroll
        for (int c = 0; c < 4; c++) {
            float4 zz = z4[lane * 4 + c], yy = yv4[lane * 4 + c];
            ul[c].x = RHO * zz.x - yy.x; ul[c].y = RHO * zz.y - yy.y;
            ul[c].z = RHO * zz.z - yy.z; ul[c].w = RHO * zz.w - yy.w;
        }
        float4 acc[4];
#pragma unroll
        for (int c = 0; c < 4; c++) acc[c] = make_float4(0.f, 0.f, 0.f, 0.f);

        row_group<0, 3>(w, lane, sY4, Yg4, ul, acc, gre, Sreg);
        row_group<3, 3>(w, lane, sY4, Yg4, ul, acc, gre, Sreg);
        row_group<6, 2>(w, lane, sY4, Yg4, ul, acc, gre, Sreg);

#pragma unroll
        for (int c = 0; c < 4; c++) redw[lane * 4 + c] = acc[c];
        __syncthreads();
        float mypart = 0.f;
#pragma unroll
        for (int w2 = 0; w2 < 16; w2++) mypart += red[w2 * 512 + tid];

        int slot = it & 1;
        uint32_t par = (uint32_t)((it >> 1) & 1);
        peerbuf[slot * 512 + tid] = mypart;
        __syncthreads();
        if (tid == 0) {
            asm volatile("fence.acq_rel.cluster;" ::: "memory");
            asm volatile(
                "{ .reg .b32 rem; mapa.shared::cluster.u32 rem, %0, %1;\n\t"
                "mbarrier.arrive.release.cluster.shared::cluster.b64 _, [rem]; }"
                :: "r"(mb_u32 + 8 * slot), "r"(peer) : "memory");
        }
        {
            uint32_t addr = mb_u32 + 8 * slot, done;
            asm volatile(
                "{ .reg .pred p;\n\t"
                "mbarrier.try_wait.parity.acquire.cluster.shared::cta.b64 p, [%1], %2;\n\t"
                "selp.b32 %0, 1, 0, p; }"
                : "=r"(done) : "r"(addr), "r"(par) : "memory");
            if (!done) {
                asm volatile(
                    "{ .reg .pred P1;\n\t"
                    "WL_%=:\n\t"
                    "mbarrier.try_wait.parity.acquire.cluster.shared::cta.b64 P1, [%0], %1, 0x989680;\n\t"
                    "@P1 bra.uni WD_%=;\n\t"
                    "bra.uni WL_%=;\n\t"
                    "WD_%=: }"
                    :: "r"(addr), "r"(par) : "memory");
            }
        }
        float zt = mypart + sbuf[slot * 512 + tid];
        float zr = ALPHA * zt + (1.0f - ALPHA) * sz[tid];
        float zc = zr + sy[tid] * (1.0f / RHO);
        float zn = fminf(fmaxf(zc, sl[tid]), sub[tid]);
        sy[tid] = sy[tid] + RHO * (zr - zn);
        sz[tid] = zn;
    }
    if (lane == 0) {
#pragma unroll
        for (int r = 0; r < 8; r++)
            g_S[b * NN + half * 128 + w + 16 * r] = Sreg[r];
    }
    cluster.sync();
}

// K6: x = Linv^T * S  -> d_out
__global__ __launch_bounds__(256) void k6_final(float* __restrict__ out)
{
    int b = blockIdx.x, tid = threadIdx.x;
    int lane = tid & 31, w = tid >> 5;
    __shared__ float sS[NN];
    __shared__ float red6[8][NN];
    sS[tid] = g_S[b * NN + tid];
    __syncthreads();
    const float* Lb = g_Linv + (size_t)b * TRI;
    float acc[8];
#pragma unroll
    for (int c = 0; c < 8; c++) acc[c] = 0.f;
    for (int n = w; n < NN; n += 8) {
        const float* row = Lb + offr(n);
        float sv = sS[n];
#pragma unroll
        for (int c = 0; c < 8; c++) {
            int i = lane + 32 * c;
            if (i <= n) acc[c] = fmaf(sv, row[i], acc[c]);
        }
    }
#pragma unroll
    for (int c = 0; c < 8; c++) red6[w][lane + 32 * c] = acc[c];
    __syncthreads();
    float x = 0.f;
#pragma unroll
    for (int w2 = 0; w2 < 8; w2++) x += red6[w2][tid];
    out[b * NN + tid] = x;
}

extern "C" void kernel_launch(void* const* d_in, const int* in_sizes, int n_in,
                              void* d_out, int out_size)
{
    const float* P = (const float*)d_in[0];
    const float* q = (const float*)d_in[1];
    const float* A = (const float*)d_in[2];
    const float* l = (const float*)d_in[3];
    const float* u = (const float*)d_in[4];
    float* out = (float*)d_out;

    int smem_k23 = (TRI + 2 * 8 * 32 * 33) * 4;   // 199,168 B
    int smem_k5 = SM5_FLOATS * 4;                 // 208,912 B
    cudaFuncSetAttribute(k23_blocked, cudaFuncAttributeMaxDynamicSharedMemorySize, smem_k23);
    cudaFuncSetAttribute(k5_iter, cudaFuncAttributeMaxDynamicSharedMemorySize, smem_k5);

    k1_buildM<<<dim3(10, BATCH), 256>>>(P, A);
    k23_blocked<<<BATCH, 512, smem_k23>>>();
    k4_Y<<<dim3(8, 4, BATCH), 256>>>(A);
    k5_iter<<<BATCH * 2, 512, smem_k5>>>(l, u, q);
    k6_final<<<BATCH, 256>>>(out);
}

// round 12
// speedup vs baseline: 1.5536x; 1.0067x over previous
#include <cuda_runtime.h>
#include <cooperative_groups.h>
#include <math.h>
#include <stdint.h>

namespace cg = cooperative_groups;

#define BATCH 64
#define NN    256
#define MM    512
#define SIGMA 1e-6f
#define RHO   0.1f
#define ALPHA 1.6f
#define ITERS 200
#define TRI   32896   // 256*257/2
#define RR    90      // Y rows resident in SMEM per half-CTA (of 128)

__device__ float g_Linv[BATCH * TRI];
__device__ float g_M[BATCH * TRI];
__device__ float g_Y[BATCH * NN * MM];
__device__ float g_S[BATCH * NN];
__device__ float g_dummy[32];

__device__ __forceinline__ int offr(int i) { return (i * (i + 1)) >> 1; }
__constant__ int c_ti[10] = {0,1,1,2,2,2,3,3,3,3};
__constant__ int c_tj[10] = {0,0,1,0,1,2,0,1,2,3};

__device__ __forceinline__ uint32_t smem_u32(const void* p) {
    uint32_t a;
    asm("{ .reg .u64 t; cvta.to.shared.u64 t, %1; cvt.u32.u64 %0, t; }"
        : "=r"(a) : "l"(p));
    return a;
}

// K0: no-op launch-position shim (shifts ncu's position-4 capture onto k23)
__global__ void k0_nop() {
    if (blockIdx.x == 0 && threadIdx.x < 32) g_dummy[threadIdx.x] = 0.f;
}

// K1: M = diag(P)+sigma*I+rho*A^T A (packed lower). 64x64 tiles, 4x4 regs.
__global__ __launch_bounds__(256) void k1_buildM(const float* __restrict__ Pv,
                                                 const float* __restrict__ Av)
{
    int p = blockIdx.x, b = blockIdx.y;
    int i0 = c_ti[p] * 64, j0 = c_tj[p] * 64;
    __shared__ float As[16][64], Bs[16][64];
    const float* A = Av + (size_t)b * (MM * NN);
    float acc[4][4];
#pragma unroll
    for (int a = 0; a < 4; a++)
#pragma unroll
        for (int c = 0; c < 4; c++) acc[a][c] = 0.f;
    int t = threadIdx.x, tx = t & 15, ty = t >> 4;
    for (int k0 = 0; k0 < MM; k0 += 16) {
#pragma unroll
        for (int r = 0; r < 4; r++) {
            int idx = t + 256 * r, kk = idx >> 6, ii = idx & 63;
            As[kk][ii] = A[(k0 + kk) * NN + i0 + ii];
            Bs[kk][ii] = A[(k0 + kk) * NN + j0 + ii];
        }
        __syncthreads();
#pragma unroll
        for (int kk = 0; kk < 16; kk++) {
            float a[4], c[4];
#pragma unroll
            for (int x = 0; x < 4; x++) { a[x] = As[kk][ty + 16 * x]; c[x] = Bs[kk][tx + 16 * x]; }
#pragma unroll
            for (int ii = 0; ii < 4; ii++)
#pragma unroll
                for (int jj = 0; jj < 4; jj++) acc[ii][jj] = fmaf(a[ii], c[jj], acc[ii][jj]);
        }
        __syncthreads();
    }
    float* Mb = g_M + (size_t)b * TRI;
#pragma unroll
    for (int ii = 0; ii < 4; ii++) {
        int i = i0 + ty + 16 * ii;
#pragma unroll
        for (int jj = 0; jj < 4; jj++) {
            int j = j0 + tx + 16 * jj;
            if (j <= i) {
                float vv = RHO * acc[ii][jj];
                if (i == j) vv += Pv[b * NN + i] + SIGMA;
                Mb[offr(i) + j] = vv;
            }
        }
    }
}

// K23: BLOCKED Cholesky + BLOCKED triangular inverse. 512 threads, NB=32.
__global__ __launch_bounds__(512) void k23_blocked()
{
    int b = blockIdx.x, tid = threadIdx.x;
    int lane = tid & 31, w = tid >> 5;   // 16 warps
    extern __shared__ float smf[];
    float* Ls   = smf;                   // TRI
    float* Dnv  = smf + TRI;             // 8*32*33: Dnv[J][c*33+i] = (L_JJ^-1)[i][c]
    float* Tmp  = Dnv + 8 * 32 * 33;     // 8*32*33: Tmp[J][r*33+c]
    const float* Mb = g_M + (size_t)b * TRI;
    float* Lb = g_Linv + (size_t)b * TRI;

    for (int i = tid; i < TRI; i += 512) Ls[i] = Mb[i];
    for (int i = tid; i < 8 * 32 * 33; i += 512) Dnv[i] = 0.f;
    __syncthreads();

    // ---------------- blocked Cholesky ----------------
    for (int K = 0; K < 8; K++) {
        int ib = K * 32;
        // 1. diag block factor (warp 0)
        if (w == 0) {
            for (int k = 0; k < 32; k++) {
                int ik = ib + k;
                float piv = Ls[offr(ik) + ik];
                float s = sqrtf(piv), rinv = 1.0f / s;
                float v = 0.f;
                if (lane == k) Ls[offr(ik) + ik] = s;
                if (lane > k) {
                    v = Ls[offr(ib + lane) + ik] * rinv;
                    Ls[offr(ib + lane) + ik] = v;
                }
                __syncwarp();
                int rowo = offr(ib + lane) + ib;
                for (int c = k + 1; c < 32; c++) {
                    float vc = __shfl_sync(0xffffffffu, v, c);
                    if (lane > k && c <= lane) Ls[rowo + c] -= v * vc;
                }
                __syncwarp();
            }
        }
        __syncthreads();
        // 2. panel TRSM: thread-per-row forward substitution (x L_KK^T = a)
        int rows_below = 256 - (K + 1) * 32;
        if (tid < rows_below) {
            int i = (K + 1) * 32 + tid;
            int rb = offr(i) + ib;
            float x[32];
#pragma unroll
            for (int j = 0; j < 32; j++) {
                float xj = Ls[rb + j];
#pragma unroll
                for (int kk = 0; kk < j; kk++)
                    xj -= x[kk] * Ls[offr(ib + j) + ib + kk];
                x[j] = xj / Ls[offr(ib + j) + ib + j];
            }
#pragma unroll
            for (int j = 0; j < 32; j++) Ls[rb + j] = x[j];
        }
        __syncthreads();
        // 3. trailing SYRK: warp-per-tile, lane = column
        if (rows_below > 0) {
            int nb2 = 7 - K;
            int T = nb2 * (nb2 + 1) / 2;
            for (int t = w; t < T; t += 16) {
                int bi2 = 0;
                while ((bi2 + 1) * (bi2 + 2) / 2 <= t) bi2++;
                int bj2 = t - bi2 * (bi2 + 1) / 2;
                int I = K + 1 + bi2, J = K + 1 + bj2;
                float lj[32];
                int cj = offr(J * 32 + lane) + ib;
#pragma unroll
                for (int k = 0; k < 32; k++) lj[k] = Ls[cj + k];
                for (int r = 0; r < 32; r++) {
                    int ri = offr(I * 32 + r);
                    float acc = Ls[ri + J * 32 + lane];   // OOB-row read ok (in-array), write-guarded
                    int rb2 = ri + ib;
#pragma unroll
                    for (int k = 0; k < 32; k++)
                        acc -= Ls[rb2 + k] * lj[k];
                    if (I != J || lane <= r) Ls[ri + J * 32 + lane] = acc;
                }
            }
        }
        __syncthreads();
    }

    // ---------------- blocked trinv ----------------
    // D_J = L_JJ^{-1}: warp J, lane c owns column c (lane-private, no shfl)
    if (w < 8) {
        int J = w, jb = J * 32;
        float* D = Dnv + J * 32 * 33;
        for (int i = 0; i < 32; i++) {
            float Lii = Ls[offr(jb + i) + jb + i];
            if (i == lane) {
                D[lane * 33 + i] = 1.0f / Lii;
            } else if (i > lane) {
                float s = 0.f;
                for (int k = lane; k < i; k++)
                    s += Ls[offr(jb + i) + jb + k] * D[lane * 33 + k];
                D[lane * 33 + i] = -s / Lii;
            }
        }
        // write diag block of Linv (lower part only; upper is structurally 0)
        for (int i = 0; i < 32; i++)
            if (lane <= i) Lb[offr(jb + i) + jb + lane] = D[lane * 33 + i];
    }
    __syncthreads();

    // column phase: Linv[I][J] = -D_I * (sum_{K2=J}^{I-1} L[I][K2] Linv[K2][J])
    // pair of warps per J: J = w&7, half h = w>>3 owns rows [16h,16h+16)
    {
        int J = w & 7, h = w >> 3, jb = J * 32;
        int r0 = h * 16;
        float* TJ = Tmp + J * 32 * 33;
        for (int I = J + 1; I < 8; I++) {
            int ibb = I * 32;
            float accr[16];
#pragma unroll
            for (int r2 = 0; r2 < 16; r2++) accr[r2] = 0.f;
            for (int K2 = J; K2 < I; K2++) {
                int kb = K2 * 32;
                float lv[32];
#pragma unroll
                for (int k = 0; k < 32; k++) {
                    // packed-triangular guard: diag block entries lane>k are
                    // structurally zero and must not be read (row aliasing).
                    float val = 0.f;
                    if (K2 != J || lane <= k)
                        val = Lb[offr(kb + k) + jb + lane];
                    lv[k] = val;
                }
#pragma unroll
                for (int r2 = 0; r2 < 16; r2++) {
                    int ro = offr(ibb + r0 + r2) + kb;
                    float a = accr[r2];
#pragma unroll
                    for (int k = 0; k < 32; k++)
                        a = fmaf(Ls[ro + k], lv[k], a);     // broadcast * reg
                    accr[r2] = a;
                }
            }
#pragma unroll
            for (int r2 = 0; r2 < 16; r2++)
                TJ[(r0 + r2) * 33 + lane] = accr[r2];
            asm volatile("bar.sync %0, %1;" :: "r"(J + 1), "r"(64) : "memory");
            {
                float tv[32];
#pragma unroll
                for (int s2 = 0; s2 < 32; s2++) tv[s2] = TJ[s2 * 33 + lane];
                float* DI = Dnv + I * 32 * 33;
#pragma unroll
                for (int r2 = 0; r2 < 16; r2++) {
                    float o = 0.f;
#pragma unroll
                    for (int s2 = 0; s2 < 32; s2++)
                        o = fmaf(DI[s2 * 33 + (r0 + r2)], tv[s2], o);  // broadcast * reg
                    Lb[offr(ibb + r0 + r2) + jb + lane] = -o;
                }
            }
            asm volatile("bar.sync %0, %1;" :: "r"(J + 1), "r"(64) : "memory");
        }
    }
}

// K4: Y[n][m] = sum_{j<=n} Linv[n][j]*A[m][j]
__global__ __launch_bounds__(256) void k4_Y(const float* __restrict__ Av)
{
    int b = blockIdx.z;
    int m0 = blockIdx.x * 64, n0 = blockIdx.y * 64;
    __shared__ float As[16][65], Bs[16][65];
    const float* Lb = g_Linv + (size_t)b * TRI;
    const float* A = Av + (size_t)b * (MM * NN);
    float acc[4][4];
#pragma unroll
    for (int a = 0; a < 4; a++)
#pragma unroll
        for (int c = 0; c < 4; c++) acc[a][c] = 0.f;
    int t = threadIdx.x, tx = t & 15, ty = t >> 4;
    int kmax = n0 + 64;
    for (int k0 = 0; k0 < kmax; k0 += 16) {
#pragma unroll
        for (int r = 0; r < 4; r++) {
            int idx = t + 256 * r, jj = idx & 15, nn = idx >> 4;
            int n = n0 + nn, j = k0 + jj;
            As[jj][nn] = (j <= n) ? Lb[offr(n) + j] : 0.f;
            Bs[jj][nn] = A[(m0 + nn) * NN + j];
        }
        __syncthreads();
#pragma unroll
        for (int jj = 0; jj < 16; jj++) {
            float a[4], c[4];
#pragma unroll
            for (int x = 0; x < 4; x++) { a[x] = As[jj][ty + 16 * x]; c[x] = Bs[jj][tx + 16 * x]; }
#pragma unroll
            for (int ii = 0; ii < 4; ii++)
#pragma unroll
                for (int cc = 0; cc < 4; cc++) acc[ii][cc] = fmaf(a[ii], c[cc], acc[ii][cc]);
        }
        __syncthreads();
    }
#pragma unroll
    for (int ii = 0; ii < 4; ii++) {
        int n = n0 + ty + 16 * ii;
#pragma unroll
        for (int cc = 0; cc < 4; cc++) {
            int m = m0 + tx + 16 * cc;
            g_Y[((size_t)b * NN + n) * MM + m] = acc[ii][cc];
        }
    }
}

// ---- K5 batched row group: dots first, then interleaved butterflies ----
// Residency is a runtime warp-uniform branch: row n resident iff n < RR.
template<int R0, int CNT>
__device__ __forceinline__ void row_group(int w, int lane,
    const float4* __restrict__ sY4, const float4* __restrict__ Yg4,
    const float4 ul[4], float4 acc[4], const float gre[8], float Sreg[8])
{
    float4 y[CNT][4];
#pragma unroll
    for (int k = 0; k < CNT; k++) {
        int n = w + 16 * (R0 + k);
        const float4* src = (n < RR) ? (sY4 + (size_t)n * 128)
                                     : (Yg4 + (size_t)n * 128);
#pragma unroll
        for (int c = 0; c < 4; c++) y[k][c] = src[lane * 4 + c];
    }
    float s[CNT];
#pragma unroll
    for (int k = 0; k < CNT; k++) {
        float t = 0.f;
#pragma unroll
        for (int c = 0; c < 4; c++)
            t += y[k][c].x * ul[c].x + y[k][c].y * ul[c].y
               + y[k][c].z * ul[c].z + y[k][c].w * ul[c].w;
        s[k] = t;
    }
#pragma unroll
    for (int o = 16; o; o >>= 1)
#pragma unroll
        for (int k = 0; k < CNT; k++)
            s[k] += __shfl_xor_sync(0xFFFFFFFFu, s[k], o);
#pragma unroll
    for (int k = 0; k < CNT; k++) {
        s[k] -= gre[R0 + k];
        Sreg[R0 + k] = (1.0f - ALPHA) * Sreg[R0 + k] + ALPHA * s[k];
#pragma unroll
        for (int c = 0; c < 4; c++) {
            acc[c].x = fmaf(s[k], y[k][c].x, acc[c].x);
            acc[c].y = fmaf(s[k], y[k][c].y, acc[c].y);
            acc[c].z = fmaf(s[k], y[k][c].z, acc[c].z);
            acc[c].w = fmaf(s[k], y[k][c].w, acc[c].w);
        }
    }
}

// K5: 200 ADMM iterations. Cluster-2 per batch; RR/128 rows SMEM-resident.
#define SM5_FLOATS (4 + RR * 512 + 16 * 512 + 4 * 512 + 2 * 512)
__global__ __cluster_dims__(2, 1, 1) __launch_bounds__(512, 1)
void k5_iter(const float* __restrict__ lv, const float* __restrict__ uv,
             const float* __restrict__ qv)
{
    cg::cluster_group cluster = cg::this_cluster();
    int b = blockIdx.x >> 1, half = blockIdx.x & 1;
    int tid = threadIdx.x, lane = tid & 31, w = tid >> 5;
    extern __shared__ float sm5[];
    float* mbf  = sm5;
    float* sY   = sm5 + 4;
    float* red  = sY + RR * 512;
    float* sz   = red + 16 * 512;
    float* sy   = sz + 512;
    float* sl   = sy + 512;
    float* sub  = sl + 512;
    float* sbuf = sub + 512;

    uint32_t mb_u32 = smem_u32(mbf);
    if (tid == 0) {
        asm volatile("mbarrier.init.shared.b64 [%0], %1;" :: "r"(mb_u32), "r"(1) : "memory");
        asm volatile("mbarrier.init.shared.b64 [%0], %1;" :: "r"(mb_u32 + 8), "r"(1) : "memory");
    }

    const float* Yg = g_Y + ((size_t)b * NN + half * 128) * MM;
    const float4* Yg4 = (const float4*)Yg;
    for (int i = tid; i < RR * 128; i += 512)
        ((float4*)sY)[i] = Yg4[i];
    sz[tid] = 0.f; sy[tid] = 0.f;
    sl[tid] = lv[b * MM + tid]; sub[tid] = uv[b * MM + tid];

    float Sreg[8], gre[8];
    {
        const float* Lb = g_Linv + (size_t)b * TRI;
        const float* qb = qv + b * NN;
#pragma unroll 1
        for (int r = 0; r < 8; r++) {
            int ng = half * 128 + w + 16 * r;
            const float* row = Lb + offr(ng);
            float s = 0.f;
            for (int j = lane; j <= ng; j += 32) s = fmaf(row[j], qb[j], s);
#pragma unroll
            for (int o = 16; o; o >>= 1) s += __shfl_xor_sync(0xFFFFFFFFu, s, o);
            gre[r] = s;
            Sreg[r] = 0.f;
        }
    }
    cluster.sync();

    uint32_t peer = (uint32_t)(half ^ 1);
    float* peerbuf = cluster.map_shared_rank(sbuf, peer);
    const float4* sY4 = (const float4*)sY;
    const float4* z4 = (const float4*)sz;
    const float4* yv4 = (const float4*)sy;
    float4* redw = (float4*)(red + w * 512);

    for (int it = 0; it < ITERS; it++) {
        __syncthreads();
        float4 ul[4];
#pragma unroll
        for (int c = 0; c < 4; c++) {
            float4 zz = z4[lane * 4 + c], yy = yv4[lane * 4 + c];
            ul[c].x = RHO * zz.x - yy.x; ul[c].y = RHO * zz.y - yy.y;
            ul[c].z = RHO * zz.z - yy.z; ul[c].w = RHO * zz.w - yy.w;
        }
        float4 acc[4];
#pragma unroll
        for (int c = 0; c < 4; c++) acc[c] = make_float4(0.f, 0.f, 0.f, 0.f);

        row_group<0, 3>(w, lane, sY4, Yg4, ul, acc, gre, Sreg);
        row_group<3, 3>(w, lane, sY4, Yg4, ul, acc, gre, Sreg);
        row_group<6, 2>(w, lane, sY4, Yg4, ul, acc, gre, Sreg);

#pragma unroll
        for (int c = 0; c < 4; c++) redw[lane * 4 + c] = acc[c];
        __syncthreads();
        float mypart = 0.f;
#pragma unroll
        for (int w2 = 0; w2 < 16; w2++) mypart += red[w2 * 512 + tid];

        int slot = it & 1;
        uint32_t par = (uint32_t)((it >> 1) & 1);
        peerbuf[slot * 512 + tid] = mypart;
        __syncthreads();
        if (tid == 0) {
            asm volatile("fence.acq_rel.cluster;" ::: "memory");
            asm volatile(
                "{ .reg .b32 rem; mapa.shared::cluster.u32 rem, %0, %1;\n\t"
                "mbarrier.arrive.release.cluster.shared::cluster.b64 _, [rem]; }"
                :: "r"(mb_u32 + 8 * slot), "r"(peer) : "memory");
        }
        {
            uint32_t addr = mb_u32 + 8 * slot, done;
            asm volatile(
                "{ .reg .pred p;\n\t"
                "mbarrier.try_wait.parity.acquire.cluster.shared::cta.b64 p, [%1], %2;\n\t"
                "selp.b32 %0, 1, 0, p; }"
                : "=r"(done) : "r"(addr), "r"(par) : "memory");
            if (!done) {
                asm volatile(
                    "{ .reg .pred P1;\n\t"
                    "WL_%=:\n\t"
                    "mbarrier.try_wait.parity.acquire.cluster.shared::cta.b64 P1, [%0], %1, 0x989680;\n\t"
                    "@P1 bra.uni WD_%=;\n\t"
                    "bra.uni WL_%=;\n\t"
                    "WD_%=: }"
                    :: "r"(addr), "r"(par) : "memory");
            }
        }
        float zt = mypart + sbuf[slot * 512 + tid];
        float zr = ALPHA * zt + (1.0f - ALPHA) * sz[tid];
        float zc = zr + sy[tid] * (1.0f / RHO);
        float zn = fminf(fmaxf(zc, sl[tid]), sub[tid]);
        sy[tid] = sy[tid] + RHO * (zr - zn);
        sz[tid] = zn;
    }
    if (lane == 0) {
#pragma unroll
        for (int r = 0; r < 8; r++)
            g_S[b * NN + half * 128 + w + 16 * r] = Sreg[r];
    }
    cluster.sync();
}

// K6: x = Linv^T * S  -> d_out
__global__ __launch_bounds__(256) void k6_final(float* __restrict__ out)
{
    int b = blockIdx.x, tid = threadIdx.x;
    int lane = tid & 31, w = tid >> 5;
    __shared__ float sS[NN];
    __shared__ float red6[8][NN];
    sS[tid] = g_S[b * NN + tid];
    __syncthreads();
    const float* Lb = g_Linv + (size_t)b * TRI;
    float acc[8];
#pragma unroll
    for (int c = 0; c < 8; c++) acc[c] = 0.f;
    for (int n = w; n < NN; n += 8) {
        const float* row = Lb + offr(n);
        float sv = sS[n];
#pragma unroll
        for (int c = 0; c < 8; c++) {
            int i = lane + 32 * c;
            if (i <= n) acc[c] = fmaf(sv, row[i], acc[c]);
        }
    }
#pragma unroll
    for (int c = 0; c < 8; c++) red6[w][lane + 32 * c] = acc[c];
    __syncthreads();
    float x = 0.f;
#pragma unroll
    for (int w2 = 0; w2 < 8; w2++) x += red6[w2][tid];
    out[b * NN + tid] = x;
}

extern "C" void kernel_launch(void* const* d_in, const int* in_sizes, int n_in,
                              void* d_out, int out_size)
{
    const float* P = (const float*)d_in[0];
    const float* q = (const float*)d_in[1];
    const float* A = (const float*)d_in[2];
    const float* l = (const float*)d_in[3];
    const float* u = (const float*)d_in[4];
    float* out = (float*)d_out;

    int smem_k23 = (TRI + 2 * 8 * 32 * 33) * 4;   // 199,168 B
    int smem_k5 = SM5_FLOATS * 4;                 // 229,392 B
    cudaFuncSetAttribute(k23_blocked, cudaFuncAttributeMaxDynamicSharedMemorySize, smem_k23);
    cudaFuncSetAttribute(k5_iter, cudaFuncAttributeMaxDynamicSharedMemorySize, smem_k5);

    k0_nop<<<1, 32>>>();                          // position shims: put k23 at
    k0_nop<<<1, 32>>>();                          // launch slot 4 for ncu capture
    k1_buildM<<<dim3(10, BATCH), 256>>>(P, A);
    k23_blocked<<<BATCH, 512, smem_k23>>>();
    k4_Y<<<dim3(8, 4, BATCH), 256>>>(A);
    k5_iter<<<BATCH * 2, 512, smem_k5>>>(l, u, q);
    k6_final<<<BATCH, 256>>>(out);
}

// round 13
// speedup vs baseline: 2.4985x; 1.6082x over previous
#include <cuda_runtime.h>
#include <cooperative_groups.h>
#include <math.h>
#include <stdint.h>

namespace cg = cooperative_groups;

#define BATCH 64
#define NN    256
#define MM    512
#define SIGMA 1e-6f
#define RHO   0.1f
#define ALPHA 1.6f
#define ITERS 200
#define TRI   32896   // 256*257/2
#define RR    90      // Y rows resident in SMEM per half-CTA (of 128)

__device__ float g_Linv[BATCH * TRI];
__device__ float g_M[BATCH * TRI];
__device__ float g_Y[BATCH * NN * MM];
__device__ float g_S[BATCH * NN];
__device__ float g_dummy[32];

__device__ __forceinline__ int offr(int i) { return (i * (i + 1)) >> 1; }
__constant__ int c_ti[10] = {0,1,1,2,2,2,3,3,3,3};
__constant__ int c_tj[10] = {0,0,1,0,1,2,0,1,2,3};

__device__ __forceinline__ uint32_t smem_u32(const void* p) {
    uint32_t a;
    asm("{ .reg .u64 t; cvta.to.shared.u64 t, %1; cvt.u32.u64 %0, t; }"
        : "=r"(a) : "l"(p));
    return a;
}

// K0: no-op launch-position shim (keeps ncu's position-4 capture on k23)
__global__ void k0_nop() {
    if (blockIdx.x == 0 && threadIdx.x < 32) g_dummy[threadIdx.x] = 0.f;
}

// K1: M = diag(P)+sigma*I+rho*A^T A (packed lower). 64x64 tiles, 4x4 regs.
__global__ __launch_bounds__(256) void k1_buildM(const float* __restrict__ Pv,
                                                 const float* __restrict__ Av)
{
    int p = blockIdx.x, b = blockIdx.y;
    int i0 = c_ti[p] * 64, j0 = c_tj[p] * 64;
    __shared__ float As[16][64], Bs[16][64];
    const float* A = Av + (size_t)b * (MM * NN);
    float acc[4][4];
#pragma unroll
    for (int a = 0; a < 4; a++)
#pragma unroll
        for (int c = 0; c < 4; c++) acc[a][c] = 0.f;
    int t = threadIdx.x, tx = t & 15, ty = t >> 4;
    for (int k0 = 0; k0 < MM; k0 += 16) {
#pragma unroll
        for (int r = 0; r < 4; r++) {
            int idx = t + 256 * r, kk = idx >> 6, ii = idx & 63;
            As[kk][ii] = A[(k0 + kk) * NN + i0 + ii];
            Bs[kk][ii] = A[(k0 + kk) * NN + j0 + ii];
        }
        __syncthreads();
#pragma unroll
        for (int kk = 0; kk < 16; kk++) {
            float a[4], c[4];
#pragma unroll
            for (int x = 0; x < 4; x++) { a[x] = As[kk][ty + 16 * x]; c[x] = Bs[kk][tx + 16 * x]; }
#pragma unroll
            for (int ii = 0; ii < 4; ii++)
#pragma unroll
                for (int jj = 0; jj < 4; jj++) acc[ii][jj] = fmaf(a[ii], c[jj], acc[ii][jj]);
        }
        __syncthreads();
    }
    float* Mb = g_M + (size_t)b * TRI;
#pragma unroll
    for (int ii = 0; ii < 4; ii++) {
        int i = i0 + ty + 16 * ii;
#pragma unroll
        for (int jj = 0; jj < 4; jj++) {
            int j = j0 + tx + 16 * jj;
            if (j <= i) {
                float vv = RHO * acc[ii][jj];
                if (i == j) vv += Pv[b * NN + i] + SIGMA;
                Mb[offr(i) + j] = vv;
            }
        }
    }
}

// K23: BLOCKED Cholesky + BLOCKED triangular inverse. 512 threads, NB=32.
__global__ __launch_bounds__(512) void k23_blocked()
{
    int b = blockIdx.x, tid = threadIdx.x;
    int lane = tid & 31, w = tid >> 5;   // 16 warps
    extern __shared__ float smf[];
    float* Ls   = smf;                   // TRI
    float* Dnv  = smf + TRI;             // 8*32*33
    float* Tmp  = Dnv + 8 * 32 * 33;     // 8*32*33
    const float* Mb = g_M + (size_t)b * TRI;
    float* Lb = g_Linv + (size_t)b * TRI;

    for (int i = tid; i < TRI; i += 512) Ls[i] = Mb[i];
    for (int i = tid; i < 8 * 32 * 33; i += 512) Dnv[i] = 0.f;
    __syncthreads();

    for (int K = 0; K < 8; K++) {
        int ib = K * 32;
        if (w == 0) {
            for (int k = 0; k < 32; k++) {
                int ik = ib + k;
                float piv = Ls[offr(ik) + ik];
                float s = sqrtf(piv), rinv = 1.0f / s;
                float v = 0.f;
                if (lane == k) Ls[offr(ik) + ik] = s;
                if (lane > k) {
                    v = Ls[offr(ib + lane) + ik] * rinv;
                    Ls[offr(ib + lane) + ik] = v;
                }
                __syncwarp();
                int rowo = offr(ib + lane) + ib;
                for (int c = k + 1; c < 32; c++) {
                    float vc = __shfl_sync(0xffffffffu, v, c);
                    if (lane > k && c <= lane) Ls[rowo + c] -= v * vc;
                }
                __syncwarp();
            }
        }
        __syncthreads();
        int rows_below = 256 - (K + 1) * 32;
        if (tid < rows_below) {
            int i = (K + 1) * 32 + tid;
            int rb = offr(i) + ib;
            float x[32];
#pragma unroll
            for (int j = 0; j < 32; j++) {
                float xj = Ls[rb + j];
#pragma unroll
                for (int kk = 0; kk < j; kk++)
                    xj -= x[kk] * Ls[offr(ib + j) + ib + kk];
                x[j] = xj / Ls[offr(ib + j) + ib + j];
            }
#pragma unroll
            for (int j = 0; j < 32; j++) Ls[rb + j] = x[j];
        }
        __syncthreads();
        if (rows_below > 0) {
            int nb2 = 7 - K;
            int T = nb2 * (nb2 + 1) / 2;
            for (int t = w; t < T; t += 16) {
                int bi2 = 0;
                while ((bi2 + 1) * (bi2 + 2) / 2 <= t) bi2++;
                int bj2 = t - bi2 * (bi2 + 1) / 2;
                int I = K + 1 + bi2, J = K + 1 + bj2;
                float lj[32];
                int cj = offr(J * 32 + lane) + ib;
#pragma unroll
                for (int k = 0; k < 32; k++) lj[k] = Ls[cj + k];
                for (int r = 0; r < 32; r++) {
                    int ri = offr(I * 32 + r);
                    float acc = Ls[ri + J * 32 + lane];
                    int rb2 = ri + ib;
#pragma unroll
                    for (int k = 0; k < 32; k++)
                        acc -= Ls[rb2 + k] * lj[k];
                    if (I != J || lane <= r) Ls[ri + J * 32 + lane] = acc;
                }
            }
        }
        __syncthreads();
    }

    if (w < 8) {
        int J = w, jb = J * 32;
        float* D = Dnv + J * 32 * 33;
        for (int i = 0; i < 32; i++) {
            float Lii = Ls[offr(jb + i) + jb + i];
            if (i == lane) {
                D[lane * 33 + i] = 1.0f / Lii;
            } else if (i > lane) {
                float s = 0.f;
                for (int k = lane; k < i; k++)
                    s += Ls[offr(jb + i) + jb + k] * D[lane * 33 + k];
                D[lane * 33 + i] = -s / Lii;
            }
        }
        for (int i = 0; i < 32; i++)
            if (lane <= i) Lb[offr(jb + i) + jb + lane] = D[lane * 33 + i];
    }
    __syncthreads();

    {
        int J = w & 7, h = w >> 3, jb = J * 32;
        int r0 = h * 16;
        float* TJ = Tmp + J * 32 * 33;
        for (int I = J + 1; I < 8; I++) {
            int ibb = I * 32;
            float accr[16];
#pragma unroll
            for (int r2 = 0; r2 < 16; r2++) accr[r2] = 0.f;
            for (int K2 = J; K2 < I; K2++) {
                int kb = K2 * 32;
                float lv[32];
#pragma unroll
                for (int k = 0; k < 32; k++) {
                    float val = 0.f;
                    if (K2 != J || lane <= k)
                        val = Lb[offr(kb + k) + jb + lane];
                    lv[k] = val;
                }
#pragma unroll
                for (int r2 = 0; r2 < 16; r2++) {
                    int ro = offr(ibb + r0 + r2) + kb;
                    float a = accr[r2];
#pragma unroll
                    for (int k = 0; k < 32; k++)
                        a = fmaf(Ls[ro + k], lv[k], a);
                    accr[r2] = a;
                }
            }
#pragma unroll
            for (int r2 = 0; r2 < 16; r2++)
                TJ[(r0 + r2) * 33 + lane] = accr[r2];
            asm volatile("bar.sync %0, %1;" :: "r"(J + 1), "r"(64) : "memory");
            {
                float tv[32];
#pragma unroll
                for (int s2 = 0; s2 < 32; s2++) tv[s2] = TJ[s2 * 33 + lane];
                float* DI = Dnv + I * 32 * 33;
#pragma unroll
                for (int r2 = 0; r2 < 16; r2++) {
                    float o = 0.f;
#pragma unroll
                    for (int s2 = 0; s2 < 32; s2++)
                        o = fmaf(DI[s2 * 33 + (r0 + r2)], tv[s2], o);
                    Lb[offr(ibb + r0 + r2) + jb + lane] = -o;
                }
            }
            asm volatile("bar.sync %0, %1;" :: "r"(J + 1), "r"(64) : "memory");
        }
    }
}

// K4: Y[n][m] = sum_{j<=n} Linv[n][j]*A[m][j]
__global__ __launch_bounds__(256) void k4_Y(const float* __restrict__ Av)
{
    int b = blockIdx.z;
    int m0 = blockIdx.x * 64, n0 = blockIdx.y * 64;
    __shared__ float As[16][65], Bs[16][65];
    const float* Lb = g_Linv + (size_t)b * TRI;
    const float* A = Av + (size_t)b * (MM * NN);
    float acc[4][4];
#pragma unroll
    for (int a = 0; a < 4; a++)
#pragma unroll
        for (int c = 0; c < 4; c++) acc[a][c] = 0.f;
    int t = threadIdx.x, tx = t & 15, ty = t >> 4;
    int kmax = n0 + 64;
    for (int k0 = 0; k0 < kmax; k0 += 16) {
#pragma unroll
        for (int r = 0; r < 4; r++) {
            int idx = t + 256 * r, jj = idx & 15, nn = idx >> 4;
            int n = n0 + nn, j = k0 + jj;
            As[jj][nn] = (j <= n) ? Lb[offr(n) + j] : 0.f;
            Bs[jj][nn] = A[(m0 + nn) * NN + j];
        }
        __syncthreads();
#pragma unroll
        for (int jj = 0; jj < 16; jj++) {
            float a[4], c[4];
#pragma unroll
            for (int x = 0; x < 4; x++) { a[x] = As[jj][ty + 16 * x]; c[x] = Bs[jj][tx + 16 * x]; }
#pragma unroll
            for (int ii = 0; ii < 4; ii++)
#pragma unroll
                for (int cc = 0; cc < 4; cc++) acc[ii][cc] = fmaf(a[ii], c[cc], acc[ii][cc]);
        }
        __syncthreads();
    }
#pragma unroll
    for (int ii = 0; ii < 4; ii++) {
        int n = n0 + ty + 16 * ii;
#pragma unroll
        for (int cc = 0; cc < 4; cc++) {
            int m = m0 + tx + 16 * cc;
            g_Y[((size_t)b * NN + n) * MM + m] = acc[ii][cc];
        }
    }
}

// ---- K5 row group: CONFLICT-FREE column mapping ----
// Thread (lane, c) owns m-block (c*32 + lane) [float4 units]: byte stride 16B
// across lanes -> LDS.128 conflict-free; global reads 512B contiguous.
template<int R0, int CNT>
__device__ __forceinline__ void row_group(int w, int lane,
    const float4* __restrict__ sY4, const float4* __restrict__ Yg4,
    const float4 ul[4], float4 acc[4], const float gre[8], float Sreg[8])
{
    float4 y[CNT][4];
#pragma unroll
    for (int k = 0; k < CNT; k++) {
        int n = w + 16 * (R0 + k);
        const float4* src = (n < RR) ? (sY4 + (size_t)n * 128)
                                     : (Yg4 + (size_t)n * 128);
#pragma unroll
        for (int c = 0; c < 4; c++) y[k][c] = src[c * 32 + lane];
    }
    float s[CNT];
#pragma unroll
    for (int k = 0; k < CNT; k++) {
        float t = 0.f;
#pragma unroll
        for (int c = 0; c < 4; c++)
            t += y[k][c].x * ul[c].x + y[k][c].y * ul[c].y
               + y[k][c].z * ul[c].z + y[k][c].w * ul[c].w;
        s[k] = t;
    }
#pragma unroll
    for (int o = 16; o; o >>= 1)
#pragma unroll
        for (int k = 0; k < CNT; k++)
            s[k] += __shfl_xor_sync(0xFFFFFFFFu, s[k], o);
#pragma unroll
    for (int k = 0; k < CNT; k++) {
        s[k] -= gre[R0 + k];
        Sreg[R0 + k] = (1.0f - ALPHA) * Sreg[R0 + k] + ALPHA * s[k];
#pragma unroll
        for (int c = 0; c < 4; c++) {
            acc[c].x = fmaf(s[k], y[k][c].x, acc[c].x);
            acc[c].y = fmaf(s[k], y[k][c].y, acc[c].y);
            acc[c].z = fmaf(s[k], y[k][c].z, acc[c].z);
            acc[c].w = fmaf(s[k], y[k][c].w, acc[c].w);
        }
    }
}

// K5: 200 ADMM iterations. Cluster-2 per batch; RR/128 rows SMEM-resident.
#define SM5_FLOATS (4 + RR * 512 + 16 * 512 + 4 * 512 + 2 * 512)
__global__ __cluster_dims__(2, 1, 1) __launch_bounds__(512, 1)
void k5_iter(const float* __restrict__ lv, const float* __restrict__ uv,
             const float* __restrict__ qv)
{
    cg::cluster_group cluster = cg::this_cluster();
    int b = blockIdx.x >> 1, half = blockIdx.x & 1;
    int tid = threadIdx.x, lane = tid & 31, w = tid >> 5;
    extern __shared__ float sm5[];
    float* mbf  = sm5;
    float* sY   = sm5 + 4;
    float* red  = sY + RR * 512;
    float* sz   = red + 16 * 512;
    float* sy   = sz + 512;
    float* sl   = sy + 512;
    float* sub  = sl + 512;
    float* sbuf = sub + 512;

    uint32_t mb_u32 = smem_u32(mbf);
    if (tid == 0) {
        asm volatile("mbarrier.init.shared.b64 [%0], %1;" :: "r"(mb_u32), "r"(1) : "memory");
        asm volatile("mbarrier.init.shared.b64 [%0], %1;" :: "r"(mb_u32 + 8), "r"(1) : "memory");
    }

    const float* Yg = g_Y + ((size_t)b * NN + half * 128) * MM;
    const float4* Yg4 = (const float4*)Yg;
    for (int i = tid; i < RR * 128; i += 512)
        ((float4*)sY)[i] = Yg4[i];
    sz[tid] = 0.f; sy[tid] = 0.f;
    sl[tid] = lv[b * MM + tid]; sub[tid] = uv[b * MM + tid];

    float Sreg[8], gre[8];
    {
        const float* Lb = g_Linv + (size_t)b * TRI;
        const float* qb = qv + b * NN;
#pragma unroll 1
        for (int r = 0; r < 8; r++) {
            int ng = half * 128 + w + 16 * r;
            const float* row = Lb + offr(ng);
            float s = 0.f;
            for (int j = lane; j <= ng; j += 32) s = fmaf(row[j], qb[j], s);
#pragma unroll
            for (int o = 16; o; o >>= 1) s += __shfl_xor_sync(0xFFFFFFFFu, s, o);
            gre[r] = s;
            Sreg[r] = 0.f;
        }
    }
    cluster.sync();

    uint32_t peer = (uint32_t)(half ^ 1);
    float* peerbuf = cluster.map_shared_rank(sbuf, peer);
    const float4* sY4 = (const float4*)sY;
    const float4* z4 = (const float4*)sz;
    const float4* yv4 = (const float4*)sy;
    float4* redw = (float4*)(red + w * 512);

    for (int it = 0; it < ITERS; it++) {
        __syncthreads();
        float4 ul[4];
#pragma unroll
        for (int c = 0; c < 4; c++) {
            // conflict-free: consecutive lanes -> consecutive float4
            float4 zz = z4[c * 32 + lane], yy = yv4[c * 32 + lane];
            ul[c].x = RHO * zz.x - yy.x; ul[c].y = RHO * zz.y - yy.y;
            ul[c].z = RHO * zz.z - yy.z; ul[c].w = RHO * zz.w - yy.w;
        }
        float4 acc[4];
#pragma unroll
        for (int c = 0; c < 4; c++) acc[c] = make_float4(0.f, 0.f, 0.f, 0.f);

        row_group<0, 3>(w, lane, sY4, Yg4, ul, acc, gre, Sreg);
        row_group<3, 3>(w, lane, sY4, Yg4, ul, acc, gre, Sreg);
        row_group<6, 2>(w, lane, sY4, Yg4, ul, acc, gre, Sreg);

#pragma unroll
        for (int c = 0; c < 4; c++) redw[c * 32 + lane] = acc[c];   // conflict-free
        __syncthreads();
        float mypart = 0.f;
#pragma unroll
        for (int w2 = 0; w2 < 16; w2++) mypart += red[w2 * 512 + tid];

        int slot = it & 1;
        uint32_t par = (uint32_t)((it >> 1) & 1);
        peerbuf[slot * 512 + tid] = mypart;
        __syncthreads();
        if (tid == 0) {
            asm volatile("fence.acq_rel.cluster;" ::: "memory");
            asm volatile(
                "{ .reg .b32 rem; mapa.shared::cluster.u32 rem, %0, %1;\n\t"
                "mbarrier.arrive.release.cluster.shared::cluster.b64 _, [rem]; }"
                :: "r"(mb_u32 + 8 * slot), "r"(peer) : "memory");
        }
        {
            uint32_t addr = mb_u32 + 8 * slot, done;
            asm volatile(
                "{ .reg .pred p;\n\t"
                "mbarrier.try_wait.parity.acquire.cluster.shared::cta.b64 p, [%1], %2;\n\t"
                "selp.b32 %0, 1, 0, p; }"
                : "=r"(done) : "r"(addr), "r"(par) : "memory");
            if (!done) {
                asm volatile(
                    "{ .reg .pred P1;\n\t"
                    "WL_%=:\n\t"
                    "mbarrier.try_wait.parity.acquire.cluster.shared::cta.b64 P1, [%0], %1, 0x989680;\n\t"
                    "@P1 bra.uni WD_%=;\n\t"
                    "bra.uni WL_%=;\n\t"
                    "WD_%=: }"
                    :: "r"(addr), "r"(par) : "memory");
            }
        }
        float zt = mypart + sbuf[slot * 512 + tid];
        float zr = ALPHA * zt + (1.0f - ALPHA) * sz[tid];
        float zc = zr + sy[tid] * (1.0f / RHO);
        float zn = fminf(fmaxf(zc, sl[tid]), sub[tid]);
        sy[tid] = sy[tid] + RHO * (zr - zn);
        sz[tid] = zn;
    }
    if (lane == 0) {
#pragma unroll
        for (int r = 0; r < 8; r++)
            g_S[b * NN + half * 128 + w + 16 * r] = Sreg[r];
    }
    cluster.sync();
}

// K6: x = Linv^T * S  -> d_out
__global__ __launch_bounds__(256) void k6_final(float* __restrict__ out)
{
    int b = blockIdx.x, tid = threadIdx.x;
    int lane = tid & 31, w = tid >> 5;
    __shared__ float sS[NN];
    __shared__ float red6[8][NN];
    sS[tid] = g_S[b * NN + tid];
    __syncthreads();
    const float* Lb = g_Linv + (size_t)b * TRI;
    float acc[8];
#pragma unroll
    for (int c = 0; c < 8; c++) acc[c] = 0.f;
    for (int n = w; n < NN; n += 8) {
        const float* row = Lb + offr(n);
        float sv = sS[n];
#pragma unroll
        for (int c = 0; c < 8; c++) {
            int i = lane + 32 * c;
            if (i <= n) acc[c] = fmaf(sv, row[i], acc[c]);
        }
    }
#pragma unroll
    for (int c = 0; c < 8; c++) red6[w][lane + 32 * c] = acc[c];
    __syncthreads();
    float x = 0.f;
#pragma unroll
    for (int w2 = 0; w2 < 8; w2++) x += red6[w2][tid];
    out[b * NN + tid] = x;
}

extern "C" void kernel_launch(void* const* d_in, const int* in_sizes, int n_in,
                              void* d_out, int out_size)
{
    const float* P = (const float*)d_in[0];
    const float* q = (const float*)d_in[1];
    const float* A = (const float*)d_in[2];
    const float* l = (const float*)d_in[3];
    const float* u = (const float*)d_in[4];
    float* out = (float*)d_out;

    int smem_k23 = (TRI + 2 * 8 * 32 * 33) * 4;   // 199,168 B
    int smem_k5 = SM5_FLOATS * 4;                 // 229,392 B
    cudaFuncSetAttribute(k23_blocked, cudaFuncAttributeMaxDynamicSharedMemorySize, smem_k23);
    cudaFuncSetAttribute(k5_iter, cudaFuncAttributeMaxDynamicSharedMemorySize, smem_k5);

    k0_nop<<<1, 32>>>();
    k0_nop<<<1, 32>>>();
    k1_buildM<<<dim3(10, BATCH), 256>>>(P, A);
    k23_blocked<<<BATCH, 512, smem_k23>>>();
    k4_Y<<<dim3(8, 4, BATCH), 256>>>(A);
    k5_iter<<<BATCH * 2, 512, smem_k5>>>(l, u, q);
    k6_final<<<BATCH, 256>>>(out);
}